// round 14
// baseline (speedup 1.0000x reference)
#include <cuda_runtime.h>

#define CC   112
#define NSP  262144                     // 64^3 spatial positions
#define MTOT (CC*NSP)                   // 29360128
#define HID  448
#define NT   448                        // 14 warps: (w%7) -> 16-row group, (w/7) -> 64-pos half
#define NBLK 2048                       // spatial blocks (128 positions each)
#define GEMM_SMEM ((CC*128 + CC*CC)*4)          // 107520 B (sIn + sW)
#define MLP_SMEM  ((2*CC*128 + CC*CC)*4)        // 164864 B (xt + hc + wbuf)

// ---------------- scratch (static device memory; no allocations) ----------------
__device__ float g_bufA[MTOT];          // u, then s(branch-sum)
__device__ float g_bufB[MTOT];          // a, then x1
__device__ double2 g_part0[1024];
__device__ double2 g_part1[4096];
__device__ double2 g_part2[4096];
__device__ double2 g_part3[4096];
__device__ float g_s0[CC], g_t0[CC], g_r0[CC];
__device__ float g_s1[CC], g_t1[CC];
__device__ float g_W1eff[CC*CC], g_B1eff[CC];
__device__ float g_W3eff[CC*CC], g_B3tot[CC];
__device__ float g_W4eff[HID*CC], g_B4eff[HID];

// ---------------- helpers ----------------
__device__ __forceinline__ float2 ffma2(float2 a, float2 b, float2 c) {
    unsigned long long ua = *reinterpret_cast<unsigned long long*>(&a);
    unsigned long long ub = *reinterpret_cast<unsigned long long*>(&b);
    unsigned long long uc = *reinterpret_cast<unsigned long long*>(&c);
    unsigned long long ud;
    asm("fma.rn.f32x2 %0, %1, %2, %3;" : "=l"(ud) : "l"(ua), "l"(ub), "l"(uc));
    return *reinterpret_cast<float2*>(&ud);
}

__device__ __forceinline__ float gelu_f(float v) {
    return 0.5f * v * (1.0f + erff(v * 0.7071067811865476f));
}

// register-tiled GEMM core, 16 rows x 2 positions per thread.
// row0 warp-uniform -> weight LDS.128 are address-uniform broadcasts (1 phase).
// xv is a float2 (256B/warp = 2 phases). Per 4k per warp: 24 crossbar phases
// vs 64 ffma2 -> fma-pipe-bound at SM level (336 < 448 cycles per 4k).
__device__ __forceinline__ void mma_core(const float* __restrict__ sIn,
                                         const float* __restrict__ sW,
                                         int row0, int px, float2 (&acc)[16]) {
#pragma unroll 1
    for (int k0 = 0; k0 < CC; k0 += 4) {
        float4 wv[16];
#pragma unroll
        for (int r = 0; r < 16; r++)
            wv[r] = *reinterpret_cast<const float4*>(sW + (row0 + r) * CC + k0);
#pragma unroll
        for (int kk = 0; kk < 4; kk++) {
            float2 xv = *reinterpret_cast<const float2*>(sIn + (k0 + kk) * 128 + px);
#pragma unroll
            for (int r = 0; r < 16; r++) {
                float w = (kk == 0) ? wv[r].x : (kk == 1) ? wv[r].y
                        : (kk == 2) ? wv[r].z : wv[r].w;
                acc[r] = ffma2(xv, make_float2(w, w), acc[r]);
            }
        }
    }
}

// block partial (sum, sumsq) -> out[blockIdx.x]; supports up to 16 warps
__device__ __forceinline__ void block_part(float fs, float fq, double2* out) {
    double s = fs, q = fq;
#pragma unroll
    for (int o = 16; o; o >>= 1) {
        s += __shfl_down_sync(0xffffffffu, s, o);
        q += __shfl_down_sync(0xffffffffu, q, o);
    }
    __shared__ double ws[16], wq[16];
    int w = threadIdx.x >> 5, l = threadIdx.x & 31;
    if (!l) { ws[w] = s; wq[w] = q; }
    __syncthreads();
    if (!threadIdx.x) {
        double ts = 0, tq = 0;
        int nw = blockDim.x >> 5;
        for (int i = 0; i < nw; i++) { ts += ws[i]; tq += wq[i]; }
        out[blockIdx.x] = make_double2(ts, tq);
    }
}

// reduce partials -> (mean, rstd) broadcast via shared mr[2]; 256 threads
__device__ __forceinline__ void stats_reduce(const double2* part, int n, float* mr) {
    int tid = threadIdx.x;
    double s = 0, q = 0;
    for (int i = tid; i < n; i += 1024) {
        double2 a = part[i];
        double2 b = (i + 256 < n) ? part[i + 256] : make_double2(0.0, 0.0);
        double2 c = (i + 512 < n) ? part[i + 512] : make_double2(0.0, 0.0);
        double2 d = (i + 768 < n) ? part[i + 768] : make_double2(0.0, 0.0);
        s += (a.x + b.x) + (c.x + d.x);
        q += (a.y + b.y) + (c.y + d.y);
    }
#pragma unroll
    for (int o = 16; o; o >>= 1) {
        s += __shfl_down_sync(0xffffffffu, s, o);
        q += __shfl_down_sync(0xffffffffu, q, o);
    }
    __shared__ double ws[8], wq[8];
    int w = tid >> 5, l = tid & 31;
    if (!l) { ws[w] = s; wq[w] = q; }
    __syncthreads();
    if (!tid) {
        double ts = 0, tq = 0;
        for (int i = 0; i < 8; i++) { ts += ws[i]; tq += wq[i]; }
        double mean = ts / (double)MTOT;
        double var  = tq / (double)MTOT - mean * mean;
        mr[0] = (float)mean;
        mr[1] = (float)rsqrt(var + 1e-5);
    }
    __syncthreads();
}

// ---------------- K0: stats of x ----------------
__global__ void k0_stats(const float* __restrict__ x) {
    int tid = blockIdx.x * blockDim.x + threadIdx.x;
    const float4* x4 = reinterpret_cast<const float4*>(x);
    float fs = 0.f, fq = 0.f;
    for (int i = tid; i < MTOT / 4; i += 262144) {
        float4 v = x4[i];
        fs += v.x + v.y + v.z + v.w;
        fq += fmaf(v.x, v.x, fmaf(v.y, v.y, fmaf(v.z, v.z, v.w * v.w)));
    }
    block_part(fs, fq, g_part0);
}

// ---------------- F0: gn1 stats -> fold into conv1 ----------------
__global__ void f0_fin(const float* __restrict__ c1w, const float* __restrict__ c1b,
                       const float* __restrict__ n1g, const float* __restrict__ n1b) {
    __shared__ float mr[2];
    __shared__ float t0s[CC];
    stats_reduce(g_part0, 1024, mr);
    int tid = threadIdx.x;
    if (tid < CC) {
        float sc = mr[1] * n1g[tid];
        float tt = n1b[tid] - mr[0] * sc;
        g_s0[tid] = sc;
        g_t0[tid] = tt;
        t0s[tid]  = tt;
        g_r0[tid] = 1.0f + sc;
    }
    __syncthreads();
    for (int t = tid; t < CC * CC; t += 256) g_W1eff[t] = c1w[t] * g_s0[t % CC];
    if (tid < CC) {
        float acc = c1b[tid];
#pragma unroll 4
        for (int c = 0; c < CC; c++) acc += c1w[tid * CC + c] * t0s[c];
        g_B1eff[tid] = acc;
    }
}

// ---------------- K1: u = conv1(gn1(x)) -> bufA, + stats of u ----------------
__global__ __launch_bounds__(NT) void k1_conv1(const float* __restrict__ x) {
    extern __shared__ float sm[];
    float* sIn = sm;                    // [112][128]
    float* sW  = sm + CC * 128;         // [112][112]
    int tid = threadIdx.x;
    int base = blockIdx.x * 128;
    for (int t = tid; t < CC * 32; t += NT) {        // float4 granularity
        int c = t >> 5, q = t & 31;
        reinterpret_cast<float4*>(sIn)[t] =
            reinterpret_cast<const float4*>(x + c * NSP + base)[q];
    }
    for (int t = tid; t < 3136; t += NT)
        reinterpret_cast<float4*>(sW)[t] = reinterpret_cast<const float4*>(g_W1eff)[t];
    __syncthreads();
    int wid = tid >> 5, lane = tid & 31;
    int row0 = (wid % 7) * 16, px = (wid / 7) * 64 + lane * 2;
    float2 acc[16];
#pragma unroll
    for (int r = 0; r < 16; r++) {
        float b = g_B1eff[row0 + r];
        acc[r] = make_float2(b, b);
    }
    mma_core(sIn, sW, row0, px, acc);
    float fs = 0.f, fq = 0.f;
#pragma unroll
    for (int r = 0; r < 16; r++) {
        *reinterpret_cast<float2*>(g_bufA + (row0 + r) * NSP + base + px) = acc[r];
        fs += acc[r].x + acc[r].y;
        fq += acc[r].x * acc[r].x + acc[r].y * acc[r].y;
    }
    block_part(fs, fq, g_part1);
}

// ---------------- F1: gn(na1) params ----------------
__global__ void f1_fin(const float* __restrict__ na1g, const float* __restrict__ na1b) {
    __shared__ float mr[2];
    stats_reduce(g_part1, NBLK, mr);
    int tid = threadIdx.x;
    if (tid < CC) {
        float sc = mr[1] * na1g[tid];
        g_s1[tid] = sc;
        g_t1[tid] = na1b[tid] - mr[0] * sc;
    }
}

// ---------------- K2: a = gelu(gn_na1(u)) : bufA -> bufB ----------------
__global__ void k2_act() {
    int i = blockIdx.x * 256 + threadIdx.x;   // 28672 blocks * 256 = MTOT/4
    float4 v = reinterpret_cast<const float4*>(g_bufA)[i];
    int c = i >> 16;                           // NSP/4 = 65536 float4 per channel
    float sc = g_s1[c], tt = g_t1[c];
    v.x = gelu_f(fmaf(v.x, sc, tt));
    v.y = gelu_f(fmaf(v.y, sc, tt));
    v.z = gelu_f(fmaf(v.z, sc, tt));
    v.w = gelu_f(fmaf(v.w, sc, tt));
    reinterpret_cast<float4*>(g_bufB)[i] = v;
}

// ---------------- K3: three axial-shift branch GEMMs + gelu + sum : bufB -> bufA ----------------
__global__ __launch_bounds__(NT) void k3_axial(
    const float* __restrict__ w2d, const float* __restrict__ b2d,
    const float* __restrict__ w2h, const float* __restrict__ b2h,
    const float* __restrict__ w2w, const float* __restrict__ b2w) {
    extern __shared__ float sm[];
    float* sIn = sm;                    // [112][128]
    float* sW  = sm + CC * 128;
    int tid = threadIdx.x;
    int d  = blockIdx.x >> 5;                 // 32 blocks per d-slice
    int h0 = (blockIdx.x & 31) * 2;           // two h rows per block
    int base = blockIdx.x * 128;
    int wid = tid >> 5, lane = tid & 31;
    int row0 = (wid % 7) * 16, px = (wid / 7) * 64 + lane * 2;
    float2 sum[16];
#pragma unroll
    for (int r = 0; r < 16; r++) sum[r] = make_float2(0.f, 0.f);
    for (int br = 0; br < 3; br++) {
        __syncthreads();
        const float* wsrc = (br == 0) ? w2d : (br == 1) ? w2h : w2w;
        const float* bsrc = (br == 0) ? b2d : (br == 1) ? b2h : b2w;
        for (int t = tid; t < 3136; t += NT)
            reinterpret_cast<float4*>(sW)[t] = reinterpret_cast<const float4*>(wsrc)[t];
        for (int t = tid; t < CC * 128; t += NT) {
            int c = t >> 7, j = t & 127;
            int hh = h0 + (j >> 6), w = j & 63;
            int ch = c >> 4;                        // chunk i = c/16
            float v = 0.0f;
            if (br == 0) {                           // a[c, d+3-i, hh, w]
                int dd = d + 3 - ch;
                if ((unsigned)dd < 64u) v = g_bufB[c * NSP + dd * 4096 + hh * 64 + w];
            } else if (br == 1) {                    // a[c, d-3, hh-i, w-3]
                int h2 = hh - ch;
                if (d >= 3 && h2 >= 0 && w >= 3)
                    v = g_bufB[c * NSP + (d - 3) * 4096 + h2 * 64 + (w - 3)];
            } else {                                 // a[c, d-6, hh-6, w-3-i]
                int ww = w - 3 - ch;
                if (d >= 6 && hh >= 6 && ww >= 0)
                    v = g_bufB[c * NSP + (d - 6) * 4096 + (hh - 6) * 64 + ww];
            }
            sIn[t] = v;
        }
        __syncthreads();
        float2 acc[16];
#pragma unroll
        for (int r = 0; r < 16; r++) {
            float b = bsrc[row0 + r];
            acc[r] = make_float2(b, b);
        }
        mma_core(sIn, sW, row0, px, acc);
#pragma unroll
        for (int r = 0; r < 16; r++) {
            sum[r].x += gelu_f(acc[r].x);
            sum[r].y += gelu_f(acc[r].y);
        }
    }
    float fs = 0.f, fq = 0.f;
#pragma unroll
    for (int r = 0; r < 16; r++) {
        *reinterpret_cast<float2*>(g_bufA + (row0 + r) * NSP + base + px) = sum[r];
        fs += sum[r].x + sum[r].y;
        fq += sum[r].x * sum[r].x + sum[r].y * sum[r].y;
    }
    block_part(fs, fq, g_part2);
}

// ---------------- F2: gn(na2) -> fold into conv3; absorb h0 bias ----------------
__global__ void f2_fin(const float* __restrict__ c3w, const float* __restrict__ c3b,
                       const float* __restrict__ na2g, const float* __restrict__ na2b) {
    __shared__ float mr[2];
    __shared__ float s2s[CC], t2s[CC];
    stats_reduce(g_part2, NBLK, mr);
    int tid = threadIdx.x;
    if (tid < CC) {
        float sc = mr[1] * na2g[tid];
        s2s[tid] = sc;
        t2s[tid] = na2b[tid] - mr[0] * sc;
    }
    __syncthreads();
    for (int t = tid; t < CC * CC; t += 256) g_W3eff[t] = c3w[t] * s2s[t % CC];
    if (tid < CC) {
        float acc = c3b[tid];
#pragma unroll 4
        for (int c = 0; c < CC; c++) acc += c3w[tid * CC + c] * t2s[c];
        g_B3tot[tid] = acc + g_t0[tid];   // + h0 bias term
    }
}

// ---------------- K5: x1 = conv3(gn_na2(s)) + h0 + x : bufA -> bufB ----------------
__global__ __launch_bounds__(NT) void k5_conv3(const float* __restrict__ x) {
    extern __shared__ float sm[];
    float* sIn = sm;                    // [112][128]
    float* sW  = sm + CC * 128;
    int tid = threadIdx.x;
    int base = blockIdx.x * 128;
    for (int t = tid; t < CC * 32; t += NT) {
        int c = t >> 5, q = t & 31;
        reinterpret_cast<float4*>(sIn)[t] =
            reinterpret_cast<const float4*>(g_bufA + c * NSP + base)[q];
    }
    for (int t = tid; t < 3136; t += NT)
        reinterpret_cast<float4*>(sW)[t] = reinterpret_cast<const float4*>(g_W3eff)[t];
    __syncthreads();
    int wid = tid >> 5, lane = tid & 31;
    int row0 = (wid % 7) * 16, px = (wid / 7) * 64 + lane * 2;
    float2 acc[16];
#pragma unroll
    for (int r = 0; r < 16; r++) {
        float b = g_B3tot[row0 + r];
        acc[r] = make_float2(b, b);
    }
    mma_core(sIn, sW, row0, px, acc);
    float fs = 0.f, fq = 0.f;
#pragma unroll
    for (int r = 0; r < 16; r++) {
        int o = row0 + r;
        float rr = g_r0[o];
        float2 xv = *reinterpret_cast<const float2*>(x + o * NSP + base + px);
        float2 v = make_float2(acc[r].x + xv.x * rr, acc[r].y + xv.y * rr);
        *reinterpret_cast<float2*>(g_bufB + o * NSP + base + px) = v;
        fs += v.x + v.y;
        fq += v.x * v.x + v.y * v.y;
    }
    block_part(fs, fq, g_part3);
}

// ---------------- F3: gn(n2) -> fold into fc1 ----------------
__global__ void f3_fin(const float* __restrict__ fc1w, const float* __restrict__ fc1b,
                       const float* __restrict__ n2g, const float* __restrict__ n2b) {
    __shared__ float mr[2];
    __shared__ float s3s[CC], t3s[CC];
    stats_reduce(g_part3, NBLK, mr);
    int tid = threadIdx.x;
    if (tid < CC) {
        float sc = mr[1] * n2g[tid];
        s3s[tid] = sc;
        t3s[tid] = n2b[tid] - mr[0] * sc;
    }
    __syncthreads();
    for (int t = tid; t < HID * CC; t += 256) g_W4eff[t] = fc1w[t] * s3s[t % CC];
    for (int hh = tid; hh < HID; hh += 256) {
        float acc = fc1b[hh];
#pragma unroll 4
        for (int c = 0; c < CC; c++) acc += fc1w[hh * CC + c] * t3s[c];
        g_B4eff[hh] = acc;
    }
}

// ---------------- K6: fused MLP, hidden streamed through one 112x128 chunk ----------------
__global__ __launch_bounds__(NT) void k6_mlp(const float* __restrict__ fc2w,
                                             const float* __restrict__ fc2b,
                                             float* __restrict__ out) {
    extern __shared__ float sm[];
    float* xt   = sm;                   // [112][128] x1 tile (and residual source)
    float* hc   = sm + CC * 128;        // [112][128] hidden chunk
    float* wbuf = hc + CC * 128;        // [112][112]
    int tid = threadIdx.x;
    int base = blockIdx.x * 128;
    for (int t = tid; t < CC * 32; t += NT) {
        int c = t >> 5, q = t & 31;
        reinterpret_cast<float4*>(xt)[t] =
            reinterpret_cast<const float4*>(g_bufB + c * NSP + base)[q];
    }
    int wid = tid >> 5, lane = tid & 31;
    int row0 = (wid % 7) * 16, px = (wid / 7) * 64 + lane * 2;
    float2 oacc[16];
#pragma unroll
    for (int r = 0; r < 16; r++) {
        float b = fc2b[row0 + r];
        oacc[r] = make_float2(b, b);
    }
    for (int hb = 0; hb < 4; hb++) {
        __syncthreads();                              // xt ready / wbuf+hc reads done
        for (int t = tid; t < 3136; t += NT)
            reinterpret_cast<float4*>(wbuf)[t] =
                reinterpret_cast<const float4*>(g_W4eff)[hb * 3136 + t];
        __syncthreads();
        float2 acc[16];
#pragma unroll
        for (int r = 0; r < 16; r++) {
            float b = g_B4eff[hb * CC + row0 + r];
            acc[r] = make_float2(b, b);
        }
        mma_core(xt, wbuf, row0, px, acc);
#pragma unroll
        for (int r = 0; r < 16; r++) {
            float2 v = make_float2(gelu_f(acc[r].x), gelu_f(acc[r].y));
            *reinterpret_cast<float2*>(hc + (row0 + r) * 128 + px) = v;
        }
        __syncthreads();                              // hc complete; wbuf reads done
        for (int t = tid; t < 3136; t += NT) {
            int o = t / 28, kq = t % 28;              // wbuf[o][kq*4..] <- fc2w[o][hb*112+...]
            reinterpret_cast<float4*>(wbuf)[t] =
                reinterpret_cast<const float4*>(fc2w)[o * 112 + hb * 28 + kq];
        }
        __syncthreads();
        mma_core(hc, wbuf, row0, px, oacc);
    }
#pragma unroll
    for (int r = 0; r < 16; r++) {
        float2 xv = *reinterpret_cast<const float2*>(xt + (row0 + r) * 128 + px);
        float2 v = make_float2(oacc[r].x + xv.x, oacc[r].y + xv.y);
        *reinterpret_cast<float2*>(out + (row0 + r) * NSP + base + px) = v;
    }
}

// ---------------- launch ----------------
extern "C" void kernel_launch(void* const* d_in, const int* in_sizes, int n_in,
                              void* d_out, int out_size) {
    const float* x    = (const float*)d_in[0];
    const float* c1w  = (const float*)d_in[1];
    const float* c1b  = (const float*)d_in[2];
    const float* c2dw = (const float*)d_in[3];
    const float* c2db = (const float*)d_in[4];
    const float* c2hw = (const float*)d_in[5];
    const float* c2hb = (const float*)d_in[6];
    const float* c2ww = (const float*)d_in[7];
    const float* c2wb = (const float*)d_in[8];
    const float* c3w  = (const float*)d_in[9];
    const float* c3b  = (const float*)d_in[10];
    const float* fc1w = (const float*)d_in[11];
    const float* fc1b = (const float*)d_in[12];
    const float* fc2w = (const float*)d_in[13];
    const float* fc2b = (const float*)d_in[14];
    const float* n1g  = (const float*)d_in[15];
    const float* n1b  = (const float*)d_in[16];
    const float* na1g = (const float*)d_in[17];
    const float* na1b = (const float*)d_in[18];
    const float* na2g = (const float*)d_in[19];
    const float* na2b = (const float*)d_in[20];
    const float* n2g  = (const float*)d_in[21];
    const float* n2b  = (const float*)d_in[22];
    float* out = (float*)d_out;

    static bool attr_done = false;
    if (!attr_done) {
        cudaFuncSetAttribute(k1_conv1, cudaFuncAttributeMaxDynamicSharedMemorySize, GEMM_SMEM);
        cudaFuncSetAttribute(k3_axial, cudaFuncAttributeMaxDynamicSharedMemorySize, GEMM_SMEM);
        cudaFuncSetAttribute(k5_conv3, cudaFuncAttributeMaxDynamicSharedMemorySize, GEMM_SMEM);
        cudaFuncSetAttribute(k6_mlp,   cudaFuncAttributeMaxDynamicSharedMemorySize, MLP_SMEM);
        attr_done = true;
    }

    k0_stats<<<1024, 256>>>(x);
    f0_fin<<<1, 256>>>(c1w, c1b, n1g, n1b);
    k1_conv1<<<NBLK, NT, GEMM_SMEM>>>(x);                 // u -> bufA
    f1_fin<<<1, 256>>>(na1g, na1b);
    k2_act<<<28672, 256>>>();                             // a -> bufB
    k3_axial<<<NBLK, NT, GEMM_SMEM>>>(c2dw, c2db, c2hw, c2hb, c2ww, c2wb);  // s -> bufA
    f2_fin<<<1, 256>>>(c3w, c3b, na2g, na2b);
    k5_conv3<<<NBLK, NT, GEMM_SMEM>>>(x);                 // x1 -> bufB
    f3_fin<<<1, 256>>>(fc1w, fc1b, n2g, n2b);
    k6_mlp<<<NBLK, NT, MLP_SMEM>>>(fc2w, fc2b, out);
}

// round 15
// speedup vs baseline: 1.1742x; 1.1742x over previous
#include <cuda_runtime.h>

#define CC   112
#define NSP  262144                     // 64^3 spatial positions
#define MTOT (CC*NSP)                   // 29360128
#define HID  448
#define NT   448                        // 14 warps x 8 rows, 128 pos (R11 known-good)
#define NBLK 2048                       // spatial blocks (128 positions each)
#define GEMM_SMEM ((CC*128 + CC*CC)*4)          // 107520 B (sIn + sW)
#define MLP_SMEM  ((2*CC*128 + 2*CC*CC)*4)      // 215040 B (xt + hc + wb0 + wb1)

// ---------------- scratch (static device memory; no allocations) ----------------
__device__ float g_bufA[MTOT];          // u, then s(branch-sum)
__device__ float g_bufB[MTOT];          // a, then x1
__device__ double2 g_part0[1024];
__device__ double2 g_part1[4096];
__device__ double2 g_part2[4096];
__device__ double2 g_part3[4096];
__device__ float g_s0[CC], g_t0[CC], g_r0[CC];
__device__ float g_s1[CC], g_t1[CC];
__device__ float g_W1eff[CC*CC], g_B1eff[CC];
__device__ float g_W3eff[CC*CC], g_B3tot[CC];
__device__ float g_W4eff[HID*CC], g_B4eff[HID];

// ---------------- helpers ----------------
__device__ __forceinline__ float2 ffma2(float2 a, float2 b, float2 c) {
    unsigned long long ua = *reinterpret_cast<unsigned long long*>(&a);
    unsigned long long ub = *reinterpret_cast<unsigned long long*>(&b);
    unsigned long long uc = *reinterpret_cast<unsigned long long*>(&c);
    unsigned long long ud;
    asm("fma.rn.f32x2 %0, %1, %2, %3;" : "=l"(ud) : "l"(ua), "l"(ub), "l"(uc));
    return *reinterpret_cast<float2*>(&ud);
}

__device__ __forceinline__ float gelu_f(float v) {
    return 0.5f * v * (1.0f + erff(v * 0.7071067811865476f));
}

__device__ __forceinline__ void cp_async16(float4* dst_smem, const float4* src) {
    unsigned s = (unsigned)__cvta_generic_to_shared(dst_smem);
    asm volatile("cp.async.cg.shared.global [%0], [%1], 16;" :: "r"(s), "l"(src));
}
__device__ __forceinline__ void cp_commit() { asm volatile("cp.async.commit_group;"); }
__device__ __forceinline__ void cp_wait0()  { asm volatile("cp.async.wait_group 0;" ::: "memory"); }

// register-tiled GEMM core (R11 known-good): 8 rows x 4 positions per thread.
// row0 warp-uniform -> weight LDS.128 are address-uniform broadcasts.
__device__ __forceinline__ void mma_core(const float* __restrict__ sIn,
                                         const float* __restrict__ sW,
                                         int row0, int px, float2 (&acc)[8][2]) {
#pragma unroll 1
    for (int k0 = 0; k0 < CC; k0 += 4) {
        float4 wv[8];
#pragma unroll
        for (int r = 0; r < 8; r++)
            wv[r] = *reinterpret_cast<const float4*>(sW + (row0 + r) * CC + k0);
#pragma unroll
        for (int kk = 0; kk < 4; kk++) {
            float4 xv = *reinterpret_cast<const float4*>(sIn + (k0 + kk) * 128 + px);
            float2 xa = make_float2(xv.x, xv.y);
            float2 xb = make_float2(xv.z, xv.w);
#pragma unroll
            for (int r = 0; r < 8; r++) {
                float w = (kk == 0) ? wv[r].x : (kk == 1) ? wv[r].y
                        : (kk == 2) ? wv[r].z : wv[r].w;
                float2 wd = make_float2(w, w);
                acc[r][0] = ffma2(xa, wd, acc[r][0]);
                acc[r][1] = ffma2(xb, wd, acc[r][1]);
            }
        }
    }
}

// block partial (sum, sumsq) -> out[blockIdx.x]; supports up to 16 warps
__device__ __forceinline__ void block_part(float fs, float fq, double2* out) {
    double s = fs, q = fq;
#pragma unroll
    for (int o = 16; o; o >>= 1) {
        s += __shfl_down_sync(0xffffffffu, s, o);
        q += __shfl_down_sync(0xffffffffu, q, o);
    }
    __shared__ double ws[16], wq[16];
    int w = threadIdx.x >> 5, l = threadIdx.x & 31;
    if (!l) { ws[w] = s; wq[w] = q; }
    __syncthreads();
    if (!threadIdx.x) {
        double ts = 0, tq = 0;
        int nw = blockDim.x >> 5;
        for (int i = 0; i < nw; i++) { ts += ws[i]; tq += wq[i]; }
        out[blockIdx.x] = make_double2(ts, tq);
    }
}

// reduce partials -> (mean, rstd) broadcast via shared mr[2]; 256 threads
__device__ __forceinline__ void stats_reduce(const double2* part, int n, float* mr) {
    int tid = threadIdx.x;
    double s = 0, q = 0;
    for (int i = tid; i < n; i += 1024) {
        double2 a = part[i];
        double2 b = (i + 256 < n) ? part[i + 256] : make_double2(0.0, 0.0);
        double2 c = (i + 512 < n) ? part[i + 512] : make_double2(0.0, 0.0);
        double2 d = (i + 768 < n) ? part[i + 768] : make_double2(0.0, 0.0);
        s += (a.x + b.x) + (c.x + d.x);
        q += (a.y + b.y) + (c.y + d.y);
    }
#pragma unroll
    for (int o = 16; o; o >>= 1) {
        s += __shfl_down_sync(0xffffffffu, s, o);
        q += __shfl_down_sync(0xffffffffu, q, o);
    }
    __shared__ double ws[8], wq[8];
    int w = tid >> 5, l = tid & 31;
    if (!l) { ws[w] = s; wq[w] = q; }
    __syncthreads();
    if (!tid) {
        double ts = 0, tq = 0;
        for (int i = 0; i < 8; i++) { ts += ws[i]; tq += wq[i]; }
        double mean = ts / (double)MTOT;
        double var  = tq / (double)MTOT - mean * mean;
        mr[0] = (float)mean;
        mr[1] = (float)rsqrt(var + 1e-5);
    }
    __syncthreads();
}

// ---------------- K0: stats of x ----------------
__global__ void k0_stats(const float* __restrict__ x) {
    int tid = blockIdx.x * blockDim.x + threadIdx.x;
    const float4* x4 = reinterpret_cast<const float4*>(x);
    float fs = 0.f, fq = 0.f;
    for (int i = tid; i < MTOT / 4; i += 262144) {
        float4 v = x4[i];
        fs += v.x + v.y + v.z + v.w;
        fq += fmaf(v.x, v.x, fmaf(v.y, v.y, fmaf(v.z, v.z, v.w * v.w)));
    }
    block_part(fs, fq, g_part0);
}

// ---------------- F0: gn1 stats -> fold into conv1 ----------------
__global__ void f0_fin(const float* __restrict__ c1w, const float* __restrict__ c1b,
                       const float* __restrict__ n1g, const float* __restrict__ n1b) {
    __shared__ float mr[2];
    __shared__ float t0s[CC];
    stats_reduce(g_part0, 1024, mr);
    int tid = threadIdx.x;
    if (tid < CC) {
        float sc = mr[1] * n1g[tid];
        float tt = n1b[tid] - mr[0] * sc;
        g_s0[tid] = sc;
        g_t0[tid] = tt;
        t0s[tid]  = tt;
        g_r0[tid] = 1.0f + sc;
    }
    __syncthreads();
    for (int t = tid; t < CC * CC; t += 256) g_W1eff[t] = c1w[t] * g_s0[t % CC];
    if (tid < CC) {
        float acc = c1b[tid];
#pragma unroll 4
        for (int c = 0; c < CC; c++) acc += c1w[tid * CC + c] * t0s[c];
        g_B1eff[tid] = acc;
    }
}

// ---------------- K1: u = conv1(gn1(x)) -> bufA, + stats of u ----------------
__global__ __launch_bounds__(NT) void k1_conv1(const float* __restrict__ x) {
    extern __shared__ float sm[];
    float* sIn = sm;                    // [112][128]
    float* sW  = sm + CC * 128;         // [112][112]
    int tid = threadIdx.x;
    int base = blockIdx.x * 128;
    for (int t = tid; t < CC * 32; t += NT) {        // float4 granularity
        int c = t >> 5, q = t & 31;
        reinterpret_cast<float4*>(sIn)[t] =
            reinterpret_cast<const float4*>(x + c * NSP + base)[q];
    }
    for (int t = tid; t < 3136; t += NT)
        reinterpret_cast<float4*>(sW)[t] = reinterpret_cast<const float4*>(g_W1eff)[t];
    __syncthreads();
    int row0 = (tid >> 5) * 8, px = (tid & 31) * 4;  // warp-uniform row0
    float2 acc[8][2];
#pragma unroll
    for (int r = 0; r < 8; r++) {
        float b = g_B1eff[row0 + r];
        acc[r][0] = make_float2(b, b); acc[r][1] = make_float2(b, b);
    }
    mma_core(sIn, sW, row0, px, acc);
    float fs = 0.f, fq = 0.f;
#pragma unroll
    for (int r = 0; r < 8; r++) {
        float4 v = make_float4(acc[r][0].x, acc[r][0].y, acc[r][1].x, acc[r][1].y);
        *reinterpret_cast<float4*>(g_bufA + (row0 + r) * NSP + base + px) = v;
        fs += v.x + v.y + v.z + v.w;
        fq += v.x * v.x + v.y * v.y + v.z * v.z + v.w * v.w;
    }
    block_part(fs, fq, g_part1);
}

// ---------------- F1: gn(na1) params ----------------
__global__ void f1_fin(const float* __restrict__ na1g, const float* __restrict__ na1b) {
    __shared__ float mr[2];
    stats_reduce(g_part1, NBLK, mr);
    int tid = threadIdx.x;
    if (tid < CC) {
        float sc = mr[1] * na1g[tid];
        g_s1[tid] = sc;
        g_t1[tid] = na1b[tid] - mr[0] * sc;
    }
}

// ---------------- K2: a = gelu(gn_na1(u)) : bufA -> bufB ----------------
__global__ void k2_act() {
    int i = blockIdx.x * 256 + threadIdx.x;   // 28672 blocks * 256 = MTOT/4
    float4 v = reinterpret_cast<const float4*>(g_bufA)[i];
    int c = i >> 16;                           // NSP/4 = 65536 float4 per channel
    float sc = g_s1[c], tt = g_t1[c];
    v.x = gelu_f(fmaf(v.x, sc, tt));
    v.y = gelu_f(fmaf(v.y, sc, tt));
    v.z = gelu_f(fmaf(v.z, sc, tt));
    v.w = gelu_f(fmaf(v.w, sc, tt));
    reinterpret_cast<float4*>(g_bufB)[i] = v;
}

// ---------------- K3: three axial-shift branch GEMMs + gelu + sum : bufB -> bufA ----------------
__global__ __launch_bounds__(NT) void k3_axial(
    const float* __restrict__ w2d, const float* __restrict__ b2d,
    const float* __restrict__ w2h, const float* __restrict__ b2h,
    const float* __restrict__ w2w, const float* __restrict__ b2w) {
    extern __shared__ float sm[];
    float* sIn = sm;                    // [112][128]
    float* sW  = sm + CC * 128;
    int tid = threadIdx.x;
    int d  = blockIdx.x >> 5;                 // 32 blocks per d-slice
    int h0 = (blockIdx.x & 31) * 2;           // two h rows per block
    int base = blockIdx.x * 128;
    int row0 = (tid >> 5) * 8, px = (tid & 31) * 4;
    float2 sum[8][2];
#pragma unroll
    for (int r = 0; r < 8; r++) {
        sum[r][0] = make_float2(0.f, 0.f); sum[r][1] = make_float2(0.f, 0.f);
    }
    for (int br = 0; br < 3; br++) {
        __syncthreads();
        const float* wsrc = (br == 0) ? w2d : (br == 1) ? w2h : w2w;
        const float* bsrc = (br == 0) ? b2d : (br == 1) ? b2h : b2w;
        for (int t = tid; t < 3136; t += NT)
            reinterpret_cast<float4*>(sW)[t] = reinterpret_cast<const float4*>(wsrc)[t];
        for (int t = tid; t < CC * 128; t += NT) {
            int c = t >> 7, j = t & 127;
            int hh = h0 + (j >> 6), w = j & 63;
            int ch = c >> 4;                        // chunk i = c/16
            float v = 0.0f;
            if (br == 0) {                           // a[c, d+3-i, hh, w]
                int dd = d + 3 - ch;
                if ((unsigned)dd < 64u) v = g_bufB[c * NSP + dd * 4096 + hh * 64 + w];
            } else if (br == 1) {                    // a[c, d-3, hh-i, w-3]
                int h2 = hh - ch;
                if (d >= 3 && h2 >= 0 && w >= 3)
                    v = g_bufB[c * NSP + (d - 3) * 4096 + h2 * 64 + (w - 3)];
            } else {                                 // a[c, d-6, hh-6, w-3-i]
                int ww = w - 3 - ch;
                if (d >= 6 && hh >= 6 && ww >= 0)
                    v = g_bufB[c * NSP + (d - 6) * 4096 + (hh - 6) * 64 + ww];
            }
            sIn[t] = v;
        }
        __syncthreads();
        float2 acc[8][2];
#pragma unroll
        for (int r = 0; r < 8; r++) {
            float b = bsrc[row0 + r];
            acc[r][0] = make_float2(b, b); acc[r][1] = make_float2(b, b);
        }
        mma_core(sIn, sW, row0, px, acc);
#pragma unroll
        for (int r = 0; r < 8; r++) {
            sum[r][0].x += gelu_f(acc[r][0].x);
            sum[r][0].y += gelu_f(acc[r][0].y);
            sum[r][1].x += gelu_f(acc[r][1].x);
            sum[r][1].y += gelu_f(acc[r][1].y);
        }
    }
    float fs = 0.f, fq = 0.f;
#pragma unroll
    for (int r = 0; r < 8; r++) {
        float4 v = make_float4(sum[r][0].x, sum[r][0].y, sum[r][1].x, sum[r][1].y);
        *reinterpret_cast<float4*>(g_bufA + (row0 + r) * NSP + base + px) = v;
        fs += v.x + v.y + v.z + v.w;
        fq += v.x * v.x + v.y * v.y + v.z * v.z + v.w * v.w;
    }
    block_part(fs, fq, g_part2);
}

// ---------------- F2: gn(na2) -> fold into conv3; absorb h0 bias ----------------
__global__ void f2_fin(const float* __restrict__ c3w, const float* __restrict__ c3b,
                       const float* __restrict__ na2g, const float* __restrict__ na2b) {
    __shared__ float mr[2];
    __shared__ float s2s[CC], t2s[CC];
    stats_reduce(g_part2, NBLK, mr);
    int tid = threadIdx.x;
    if (tid < CC) {
        float sc = mr[1] * na2g[tid];
        s2s[tid] = sc;
        t2s[tid] = na2b[tid] - mr[0] * sc;
    }
    __syncthreads();
    for (int t = tid; t < CC * CC; t += 256) g_W3eff[t] = c3w[t] * s2s[t % CC];
    if (tid < CC) {
        float acc = c3b[tid];
#pragma unroll 4
        for (int c = 0; c < CC; c++) acc += c3w[tid * CC + c] * t2s[c];
        g_B3tot[tid] = acc + g_t0[tid];   // + h0 bias term
    }
}

// ---------------- K5: x1 = conv3(gn_na2(s)) + h0 + x : bufA -> bufB ----------------
__global__ __launch_bounds__(NT) void k5_conv3(const float* __restrict__ x) {
    extern __shared__ float sm[];
    float* sIn = sm;                    // [112][128]
    float* sW  = sm + CC * 128;
    int tid = threadIdx.x;
    int base = blockIdx.x * 128;
    for (int t = tid; t < CC * 32; t += NT) {
        int c = t >> 5, q = t & 31;
        reinterpret_cast<float4*>(sIn)[t] =
            reinterpret_cast<const float4*>(g_bufA + c * NSP + base)[q];
    }
    for (int t = tid; t < 3136; t += NT)
        reinterpret_cast<float4*>(sW)[t] = reinterpret_cast<const float4*>(g_W3eff)[t];
    __syncthreads();
    int row0 = (tid >> 5) * 8, px = (tid & 31) * 4;
    float2 acc[8][2];
#pragma unroll
    for (int r = 0; r < 8; r++) {
        float b = g_B3tot[row0 + r];
        acc[r][0] = make_float2(b, b); acc[r][1] = make_float2(b, b);
    }
    mma_core(sIn, sW, row0, px, acc);
    float fs = 0.f, fq = 0.f;
#pragma unroll
    for (int r = 0; r < 8; r++) {
        int o = row0 + r;
        float rr = g_r0[o];
        float4 xv = *reinterpret_cast<const float4*>(x + o * NSP + base + px);
        float4 v = make_float4(acc[r][0].x + xv.x * rr, acc[r][0].y + xv.y * rr,
                               acc[r][1].x + xv.z * rr, acc[r][1].y + xv.w * rr);
        *reinterpret_cast<float4*>(g_bufB + o * NSP + base + px) = v;
        fs += v.x + v.y + v.z + v.w;
        fq += v.x * v.x + v.y * v.y + v.z * v.z + v.w * v.w;
    }
    block_part(fs, fq, g_part3);
}

// ---------------- F3: gn(n2) -> fold into fc1 ----------------
__global__ void f3_fin(const float* __restrict__ fc1w, const float* __restrict__ fc1b,
                       const float* __restrict__ n2g, const float* __restrict__ n2b) {
    __shared__ float mr[2];
    __shared__ float s3s[CC], t3s[CC];
    stats_reduce(g_part3, NBLK, mr);
    int tid = threadIdx.x;
    if (tid < CC) {
        float sc = mr[1] * n2g[tid];
        s3s[tid] = sc;
        t3s[tid] = n2b[tid] - mr[0] * sc;
    }
    __syncthreads();
    for (int t = tid; t < HID * CC; t += 256) g_W4eff[t] = fc1w[t] * s3s[t % CC];
    for (int hh = tid; hh < HID; hh += 256) {
        float acc = fc1b[hh];
#pragma unroll 4
        for (int c = 0; c < CC; c++) acc += fc1w[hh * CC + c] * t3s[c];
        g_B4eff[hh] = acc;
    }
}

// ---------------- K6: fused MLP with double-buffered cp.async weight pipeline ----------------
// 8 phases (fc1[0],fc2[0],fc1[1],fc2[1],...): prefetch chunk p+1 into the idle
// weight buffer while computing chunk p. 1 barrier + 1 wait per phase.
__global__ __launch_bounds__(NT) void k6_mlp(const float* __restrict__ fc2w,
                                             const float* __restrict__ fc2b,
                                             float* __restrict__ out) {
    extern __shared__ float sm[];
    float* xt  = sm;                    // [112][128] x1 tile (residual source)
    float* hc  = sm + CC * 128;         // [112][128] hidden chunk
    float* wb0 = hc + CC * 128;         // [112][112]
    float* wb1 = wb0 + CC * CC;         // [112][112]
    int tid = threadIdx.x;
    int base = blockIdx.x * 128;

    // prologue: async stage xt + first fc1 weight chunk
    for (int t = tid; t < CC * 32; t += NT) {
        int c = t >> 5, q = t & 31;
        cp_async16(&reinterpret_cast<float4*>(xt)[t],
                   &reinterpret_cast<const float4*>(g_bufB + c * NSP + base)[q]);
    }
    for (int t = tid; t < 3136; t += NT)
        cp_async16(&reinterpret_cast<float4*>(wb0)[t],
                   &reinterpret_cast<const float4*>(g_W4eff)[t]);
    cp_commit();

    int row0 = (tid >> 5) * 8, px = (tid & 31) * 4;
    float2 oacc[8][2];
#pragma unroll
    for (int r = 0; r < 8; r++) {
        float b = fc2b[row0 + r];
        oacc[r][0] = make_float2(b, b); oacc[r][1] = make_float2(b, b);
    }

    cp_wait0();
    __syncthreads();

#pragma unroll 1
    for (int p = 0; p < 8; p++) {
        float* cur = (p & 1) ? wb1 : wb0;
        float* nxt = (p & 1) ? wb0 : wb1;
        int hb = p >> 1;
        // prefetch chunk p+1 into nxt (its last readers finished before the
        // barrier that ended phase p-1)
        if (p < 7) {
            int np = p + 1, nhb = np >> 1;
            if ((np & 1) == 0) {          // next is fc1 chunk nhb
                for (int t = tid; t < 3136; t += NT)
                    cp_async16(&reinterpret_cast<float4*>(nxt)[t],
                               &reinterpret_cast<const float4*>(g_W4eff)[nhb * 3136 + t]);
            } else {                      // next is fc2 chunk nhb
                for (int t = tid; t < 3136; t += NT) {
                    int o = t / 28, kq = t % 28;
                    cp_async16(&reinterpret_cast<float4*>(nxt)[t],
                               &reinterpret_cast<const float4*>(fc2w)[o * 112 + nhb * 28 + kq]);
                }
            }
            cp_commit();
        }
        if ((p & 1) == 0) {               // fc1 phase: hc = gelu(W4eff[hb] @ xt + b)
            float2 acc[8][2];
#pragma unroll
            for (int r = 0; r < 8; r++) {
                float b = g_B4eff[hb * CC + row0 + r];
                acc[r][0] = make_float2(b, b); acc[r][1] = make_float2(b, b);
            }
            mma_core(xt, cur, row0, px, acc);
#pragma unroll
            for (int r = 0; r < 8; r++) {
                float4 v = make_float4(gelu_f(acc[r][0].x), gelu_f(acc[r][0].y),
                                       gelu_f(acc[r][1].x), gelu_f(acc[r][1].y));
                *reinterpret_cast<float4*>(hc + (row0 + r) * 128 + px) = v;
            }
        } else {                          // fc2 phase: oacc += fc2[hb] @ hc
            mma_core(hc, cur, row0, px, oacc);
        }
        if (p < 7) cp_wait0();            // prefetch landed (overlapped with mma)
        __syncthreads();                  // orders hc writes/reads + buffer reuse
    }
#pragma unroll
    for (int r = 0; r < 8; r++) {
        float4 xv = *reinterpret_cast<const float4*>(xt + (row0 + r) * 128 + px);
        float4 v = make_float4(oacc[r][0].x + xv.x, oacc[r][0].y + xv.y,
                               oacc[r][1].x + xv.z, oacc[r][1].y + xv.w);
        *reinterpret_cast<float4*>(out + (row0 + r) * NSP + base + px) = v;
    }
}

// ---------------- launch ----------------
extern "C" void kernel_launch(void* const* d_in, const int* in_sizes, int n_in,
                              void* d_out, int out_size) {
    const float* x    = (const float*)d_in[0];
    const float* c1w  = (const float*)d_in[1];
    const float* c1b  = (const float*)d_in[2];
    const float* c2dw = (const float*)d_in[3];
    const float* c2db = (const float*)d_in[4];
    const float* c2hw = (const float*)d_in[5];
    const float* c2hb = (const float*)d_in[6];
    const float* c2ww = (const float*)d_in[7];
    const float* c2wb = (const float*)d_in[8];
    const float* c3w  = (const float*)d_in[9];
    const float* c3b  = (const float*)d_in[10];
    const float* fc1w = (const float*)d_in[11];
    const float* fc1b = (const float*)d_in[12];
    const float* fc2w = (const float*)d_in[13];
    const float* fc2b = (const float*)d_in[14];
    const float* n1g  = (const float*)d_in[15];
    const float* n1b  = (const float*)d_in[16];
    const float* na1g = (const float*)d_in[17];
    const float* na1b = (const float*)d_in[18];
    const float* na2g = (const float*)d_in[19];
    const float* na2b = (const float*)d_in[20];
    const float* n2g  = (const float*)d_in[21];
    const float* n2b  = (const float*)d_in[22];
    float* out = (float*)d_out;

    static bool attr_done = false;
    if (!attr_done) {
        cudaFuncSetAttribute(k1_conv1, cudaFuncAttributeMaxDynamicSharedMemorySize, GEMM_SMEM);
        cudaFuncSetAttribute(k3_axial, cudaFuncAttributeMaxDynamicSharedMemorySize, GEMM_SMEM);
        cudaFuncSetAttribute(k5_conv3, cudaFuncAttributeMaxDynamicSharedMemorySize, GEMM_SMEM);
        cudaFuncSetAttribute(k6_mlp,   cudaFuncAttributeMaxDynamicSharedMemorySize, MLP_SMEM);
        attr_done = true;
    }

    k0_stats<<<1024, 256>>>(x);
    f0_fin<<<1, 256>>>(c1w, c1b, n1g, n1b);
    k1_conv1<<<NBLK, NT, GEMM_SMEM>>>(x);                 // u -> bufA
    f1_fin<<<1, 256>>>(na1g, na1b);
    k2_act<<<28672, 256>>>();                             // a -> bufB
    k3_axial<<<NBLK, NT, GEMM_SMEM>>>(c2dw, c2db, c2hw, c2hb, c2ww, c2wb);  // s -> bufA
    f2_fin<<<1, 256>>>(c3w, c3b, na2g, na2b);
    k5_conv3<<<NBLK, NT, GEMM_SMEM>>>(x);                 // x1 -> bufB
    f3_fin<<<1, 256>>>(fc1w, fc1b, n2g, n2b);
    k6_mlp<<<NBLK, NT, MLP_SMEM>>>(fc2w, fc2b, out);
}

// round 16
// speedup vs baseline: 1.2654x; 1.0777x over previous
#include <cuda_runtime.h>

#define CC   112
#define NSP  262144                     // 64^3 spatial positions
#define MTOT (CC*NSP)                   // 29360128
#define HID  448
#define NT   448                        // 14 warps x 8 rows, 128 pos (R11 known-good)
#define NBLK 2048                       // spatial blocks (128 positions each)
#define GEMM_SMEM ((CC*128 + CC*CC)*4)          // 107520 B (sIn + sW)
#define PIPE_SMEM ((2*CC*128 + 2*CC*CC)*4)      // 215040 B (double-buffered in + w)

// ---------------- scratch (static device memory; no allocations) ----------------
__device__ float g_bufA[MTOT];          // u, then s(branch-sum)
__device__ float g_bufB[MTOT];          // a, then x1
__device__ double2 g_part0[1024];
__device__ double2 g_part1[4096];
__device__ double2 g_part2[4096];
__device__ double2 g_part3[4096];
__device__ float g_s0[CC], g_t0[CC], g_r0[CC];
__device__ float g_s1[CC], g_t1[CC];
__device__ float g_W1eff[CC*CC], g_B1eff[CC];
__device__ float g_W3eff[CC*CC], g_B3tot[CC];
__device__ float g_W4eff[HID*CC], g_B4eff[HID];

// ---------------- helpers ----------------
__device__ __forceinline__ float2 ffma2(float2 a, float2 b, float2 c) {
    unsigned long long ua = *reinterpret_cast<unsigned long long*>(&a);
    unsigned long long ub = *reinterpret_cast<unsigned long long*>(&b);
    unsigned long long uc = *reinterpret_cast<unsigned long long*>(&c);
    unsigned long long ud;
    asm("fma.rn.f32x2 %0, %1, %2, %3;" : "=l"(ud) : "l"(ua), "l"(ub), "l"(uc));
    return *reinterpret_cast<float2*>(&ud);
}

__device__ __forceinline__ float gelu_f(float v) {
    return 0.5f * v * (1.0f + erff(v * 0.7071067811865476f));
}

__device__ __forceinline__ void cp_async16(float4* dst_smem, const float4* src) {
    unsigned s = (unsigned)__cvta_generic_to_shared(dst_smem);
    asm volatile("cp.async.cg.shared.global [%0], [%1], 16;" :: "r"(s), "l"(src));
}
// 4-byte cp.async with predicated zero-fill via src-size operand.
__device__ __forceinline__ void cp_async4_pred(float* dst_smem, const float* src, bool valid) {
    unsigned s = (unsigned)__cvta_generic_to_shared(dst_smem);
    int sz = valid ? 4 : 0;
    asm volatile("cp.async.ca.shared.global [%0], [%1], 4, %2;"
                 :: "r"(s), "l"(src), "r"(sz));
}
__device__ __forceinline__ void cp_commit() { asm volatile("cp.async.commit_group;"); }
__device__ __forceinline__ void cp_wait0()  { asm volatile("cp.async.wait_group 0;" ::: "memory"); }

// register-tiled GEMM core (R11 known-good): 8 rows x 4 positions per thread.
// row0 warp-uniform -> weight LDS.128 are address-uniform broadcasts.
__device__ __forceinline__ void mma_core(const float* __restrict__ sIn,
                                         const float* __restrict__ sW,
                                         int row0, int px, float2 (&acc)[8][2]) {
#pragma unroll 1
    for (int k0 = 0; k0 < CC; k0 += 4) {
        float4 wv[8];
#pragma unroll
        for (int r = 0; r < 8; r++)
            wv[r] = *reinterpret_cast<const float4*>(sW + (row0 + r) * CC + k0);
#pragma unroll
        for (int kk = 0; kk < 4; kk++) {
            float4 xv = *reinterpret_cast<const float4*>(sIn + (k0 + kk) * 128 + px);
            float2 xa = make_float2(xv.x, xv.y);
            float2 xb = make_float2(xv.z, xv.w);
#pragma unroll
            for (int r = 0; r < 8; r++) {
                float w = (kk == 0) ? wv[r].x : (kk == 1) ? wv[r].y
                        : (kk == 2) ? wv[r].z : wv[r].w;
                float2 wd = make_float2(w, w);
                acc[r][0] = ffma2(xa, wd, acc[r][0]);
                acc[r][1] = ffma2(xb, wd, acc[r][1]);
            }
        }
    }
}

// block partial (sum, sumsq) -> out[blockIdx.x]; supports up to 16 warps
__device__ __forceinline__ void block_part(float fs, float fq, double2* out) {
    double s = fs, q = fq;
#pragma unroll
    for (int o = 16; o; o >>= 1) {
        s += __shfl_down_sync(0xffffffffu, s, o);
        q += __shfl_down_sync(0xffffffffu, q, o);
    }
    __shared__ double ws[16], wq[16];
    int w = threadIdx.x >> 5, l = threadIdx.x & 31;
    if (!l) { ws[w] = s; wq[w] = q; }
    __syncthreads();
    if (!threadIdx.x) {
        double ts = 0, tq = 0;
        int nw = blockDim.x >> 5;
        for (int i = 0; i < nw; i++) { ts += ws[i]; tq += wq[i]; }
        out[blockIdx.x] = make_double2(ts, tq);
    }
}

// reduce partials -> (mean, rstd) broadcast via shared mr[2]; 256 threads
__device__ __forceinline__ void stats_reduce(const double2* part, int n, float* mr) {
    int tid = threadIdx.x;
    double s = 0, q = 0;
    for (int i = tid; i < n; i += 1024) {
        double2 a = part[i];
        double2 b = (i + 256 < n) ? part[i + 256] : make_double2(0.0, 0.0);
        double2 c = (i + 512 < n) ? part[i + 512] : make_double2(0.0, 0.0);
        double2 d = (i + 768 < n) ? part[i + 768] : make_double2(0.0, 0.0);
        s += (a.x + b.x) + (c.x + d.x);
        q += (a.y + b.y) + (c.y + d.y);
    }
#pragma unroll
    for (int o = 16; o; o >>= 1) {
        s += __shfl_down_sync(0xffffffffu, s, o);
        q += __shfl_down_sync(0xffffffffu, q, o);
    }
    __shared__ double ws[8], wq[8];
    int w = tid >> 5, l = tid & 31;
    if (!l) { ws[w] = s; wq[w] = q; }
    __syncthreads();
    if (!tid) {
        double ts = 0, tq = 0;
        for (int i = 0; i < 8; i++) { ts += ws[i]; tq += wq[i]; }
        double mean = ts / (double)MTOT;
        double var  = tq / (double)MTOT - mean * mean;
        mr[0] = (float)mean;
        mr[1] = (float)rsqrt(var + 1e-5);
    }
    __syncthreads();
}

// ---------------- K0: stats of x ----------------
__global__ void k0_stats(const float* __restrict__ x) {
    int tid = blockIdx.x * blockDim.x + threadIdx.x;
    const float4* x4 = reinterpret_cast<const float4*>(x);
    float fs = 0.f, fq = 0.f;
    for (int i = tid; i < MTOT / 4; i += 262144) {
        float4 v = x4[i];
        fs += v.x + v.y + v.z + v.w;
        fq += fmaf(v.x, v.x, fmaf(v.y, v.y, fmaf(v.z, v.z, v.w * v.w)));
    }
    block_part(fs, fq, g_part0);
}

// ---------------- F0: gn1 stats -> fold into conv1 ----------------
__global__ void f0_fin(const float* __restrict__ c1w, const float* __restrict__ c1b,
                       const float* __restrict__ n1g, const float* __restrict__ n1b) {
    __shared__ float mr[2];
    __shared__ float t0s[CC];
    stats_reduce(g_part0, 1024, mr);
    int tid = threadIdx.x;
    if (tid < CC) {
        float sc = mr[1] * n1g[tid];
        float tt = n1b[tid] - mr[0] * sc;
        g_s0[tid] = sc;
        g_t0[tid] = tt;
        t0s[tid]  = tt;
        g_r0[tid] = 1.0f + sc;
    }
    __syncthreads();
    for (int t = tid; t < CC * CC; t += 256) g_W1eff[t] = c1w[t] * g_s0[t % CC];
    if (tid < CC) {
        float acc = c1b[tid];
#pragma unroll 4
        for (int c = 0; c < CC; c++) acc += c1w[tid * CC + c] * t0s[c];
        g_B1eff[tid] = acc;
    }
}

// ---------------- K1: u = conv1(gn1(x)) -> bufA, + stats of u ----------------
__global__ __launch_bounds__(NT) void k1_conv1(const float* __restrict__ x) {
    extern __shared__ float sm[];
    float* sIn = sm;                    // [112][128]
    float* sW  = sm + CC * 128;         // [112][112]
    int tid = threadIdx.x;
    int base = blockIdx.x * 128;
    for (int t = tid; t < CC * 32; t += NT) {        // float4 granularity
        int c = t >> 5, q = t & 31;
        cp_async16(&reinterpret_cast<float4*>(sIn)[t],
                   &reinterpret_cast<const float4*>(x + c * NSP + base)[q]);
    }
    for (int t = tid; t < 3136; t += NT)
        cp_async16(&reinterpret_cast<float4*>(sW)[t],
                   &reinterpret_cast<const float4*>(g_W1eff)[t]);
    cp_commit();
    cp_wait0();
    __syncthreads();
    int row0 = (tid >> 5) * 8, px = (tid & 31) * 4;  // warp-uniform row0
    float2 acc[8][2];
#pragma unroll
    for (int r = 0; r < 8; r++) {
        float b = g_B1eff[row0 + r];
        acc[r][0] = make_float2(b, b); acc[r][1] = make_float2(b, b);
    }
    mma_core(sIn, sW, row0, px, acc);
    float fs = 0.f, fq = 0.f;
#pragma unroll
    for (int r = 0; r < 8; r++) {
        float4 v = make_float4(acc[r][0].x, acc[r][0].y, acc[r][1].x, acc[r][1].y);
        *reinterpret_cast<float4*>(g_bufA + (row0 + r) * NSP + base + px) = v;
        fs += v.x + v.y + v.z + v.w;
        fq += v.x * v.x + v.y * v.y + v.z * v.z + v.w * v.w;
    }
    block_part(fs, fq, g_part1);
}

// ---------------- F1: gn(na1) params ----------------
__global__ void f1_fin(const float* __restrict__ na1g, const float* __restrict__ na1b) {
    __shared__ float mr[2];
    stats_reduce(g_part1, NBLK, mr);
    int tid = threadIdx.x;
    if (tid < CC) {
        float sc = mr[1] * na1g[tid];
        g_s1[tid] = sc;
        g_t1[tid] = na1b[tid] - mr[0] * sc;
    }
}

// ---------------- K2: a = gelu(gn_na1(u)) : bufA -> bufB ----------------
__global__ void k2_act() {
    int i = blockIdx.x * 256 + threadIdx.x;   // 28672 blocks * 256 = MTOT/4
    float4 v = reinterpret_cast<const float4*>(g_bufA)[i];
    int c = i >> 16;                           // NSP/4 = 65536 float4 per channel
    float sc = g_s1[c], tt = g_t1[c];
    v.x = gelu_f(fmaf(v.x, sc, tt));
    v.y = gelu_f(fmaf(v.y, sc, tt));
    v.z = gelu_f(fmaf(v.z, sc, tt));
    v.w = gelu_f(fmaf(v.w, sc, tt));
    reinterpret_cast<float4*>(g_bufB)[i] = v;
}

// ---------------- K3: three axial-shift branch GEMMs, fully pipelined ----------------
// Double-buffered sIn + weights; branch br+1's gather (cp.async 4B with
// predicated zero-fill) and weights stream in during branch br's mma.
__global__ __launch_bounds__(NT) void k3_axial(
    const float* __restrict__ w2d, const float* __restrict__ b2d,
    const float* __restrict__ w2h, const float* __restrict__ b2h,
    const float* __restrict__ w2w, const float* __restrict__ b2w) {
    extern __shared__ float sm[];
    float* sIn0 = sm;                    // [112][128]
    float* sIn1 = sIn0 + CC * 128;
    float* wb0  = sIn1 + CC * 128;       // [112][112]
    float* wb1  = wb0 + CC * CC;
    int tid = threadIdx.x;
    int d  = blockIdx.x >> 5;                 // 32 blocks per d-slice
    int h0 = (blockIdx.x & 31) * 2;           // two h rows per block
    int base = blockIdx.x * 128;
    int row0 = (tid >> 5) * 8, px = (tid & 31) * 4;

    // prologue: prefetch branch 0 (weights + gather)
    for (int t = tid; t < 3136; t += NT)
        cp_async16(&reinterpret_cast<float4*>(wb0)[t],
                   &reinterpret_cast<const float4*>(w2d)[t]);
    for (int t = tid; t < CC * 128; t += NT) {
        int c = t >> 7, j = t & 127;
        int hh = h0 + (j >> 6), w = j & 63;
        int ch = c >> 4;                      // chunk i = c/16
        int dd = d + 3 - ch;                  // a[c, d+3-i, hh, w]
        bool valid = ((unsigned)dd < 64u);
        int idx = valid ? (c * NSP + dd * 4096 + hh * 64 + w) : 0;
        cp_async4_pred(&sIn0[t], g_bufB + idx, valid);
    }
    cp_commit();

    float2 sum[8][2];
#pragma unroll
    for (int r = 0; r < 8; r++) {
        sum[r][0] = make_float2(0.f, 0.f); sum[r][1] = make_float2(0.f, 0.f);
    }
    cp_wait0();
    __syncthreads();

#pragma unroll 1
    for (int br = 0; br < 3; br++) {
        float* curIn = (br & 1) ? sIn1 : sIn0;
        float* curW  = (br & 1) ? wb1  : wb0;
        if (br < 2) {
            float* nIn = (br & 1) ? sIn0 : sIn1;
            float* nW  = (br & 1) ? wb0  : wb1;
            const float* wsrc = (br == 0) ? w2h : w2w;
            for (int t = tid; t < 3136; t += NT)
                cp_async16(&reinterpret_cast<float4*>(nW)[t],
                           &reinterpret_cast<const float4*>(wsrc)[t]);
            for (int t = tid; t < CC * 128; t += NT) {
                int c = t >> 7, j = t & 127;
                int hh = h0 + (j >> 6), w = j & 63;
                int ch = c >> 4;
                bool valid; int idx = 0;
                if (br == 0) {                    // next: a[c, d-3, hh-i, w-3]
                    int h2 = hh - ch;
                    valid = (d >= 3 && h2 >= 0 && w >= 3);
                    if (valid) idx = c * NSP + (d - 3) * 4096 + h2 * 64 + (w - 3);
                } else {                          // next: a[c, d-6, hh-6, w-3-i]
                    int ww = w - 3 - ch;
                    valid = (d >= 6 && hh >= 6 && ww >= 0);
                    if (valid) idx = c * NSP + (d - 6) * 4096 + (hh - 6) * 64 + ww;
                }
                cp_async4_pred(&nIn[t], g_bufB + idx, valid);
            }
            cp_commit();
        }
        const float* bsrc = (br == 0) ? b2d : (br == 1) ? b2h : b2w;
        float2 acc[8][2];
#pragma unroll
        for (int r = 0; r < 8; r++) {
            float b = bsrc[row0 + r];
            acc[r][0] = make_float2(b, b); acc[r][1] = make_float2(b, b);
        }
        mma_core(curIn, curW, row0, px, acc);
#pragma unroll
        for (int r = 0; r < 8; r++) {
            sum[r][0].x += gelu_f(acc[r][0].x);
            sum[r][0].y += gelu_f(acc[r][0].y);
            sum[r][1].x += gelu_f(acc[r][1].x);
            sum[r][1].y += gelu_f(acc[r][1].y);
        }
        if (br < 2) cp_wait0();           // prefetch landed (overlapped with mma)
        __syncthreads();                  // buffer-reuse ordering
    }
    float fs = 0.f, fq = 0.f;
#pragma unroll
    for (int r = 0; r < 8; r++) {
        float4 v = make_float4(sum[r][0].x, sum[r][0].y, sum[r][1].x, sum[r][1].y);
        *reinterpret_cast<float4*>(g_bufA + (row0 + r) * NSP + base + px) = v;
        fs += v.x + v.y + v.z + v.w;
        fq += v.x * v.x + v.y * v.y + v.z * v.z + v.w * v.w;
    }
    block_part(fs, fq, g_part2);
}

// ---------------- F2: gn(na2) -> fold into conv3; absorb h0 bias ----------------
__global__ void f2_fin(const float* __restrict__ c3w, const float* __restrict__ c3b,
                       const float* __restrict__ na2g, const float* __restrict__ na2b) {
    __shared__ float mr[2];
    __shared__ float s2s[CC], t2s[CC];
    stats_reduce(g_part2, NBLK, mr);
    int tid = threadIdx.x;
    if (tid < CC) {
        float sc = mr[1] * na2g[tid];
        s2s[tid] = sc;
        t2s[tid] = na2b[tid] - mr[0] * sc;
    }
    __syncthreads();
    for (int t = tid; t < CC * CC; t += 256) g_W3eff[t] = c3w[t] * s2s[t % CC];
    if (tid < CC) {
        float acc = c3b[tid];
#pragma unroll 4
        for (int c = 0; c < CC; c++) acc += c3w[tid * CC + c] * t2s[c];
        g_B3tot[tid] = acc + g_t0[tid];   // + h0 bias term
    }
}

// ---------------- K5: x1 = conv3(gn_na2(s)) + h0 + x : bufA -> bufB ----------------
__global__ __launch_bounds__(NT) void k5_conv3(const float* __restrict__ x) {
    extern __shared__ float sm[];
    float* sIn = sm;                    // [112][128]
    float* sW  = sm + CC * 128;
    int tid = threadIdx.x;
    int base = blockIdx.x * 128;
    for (int t = tid; t < CC * 32; t += NT) {
        int c = t >> 5, q = t & 31;
        cp_async16(&reinterpret_cast<float4*>(sIn)[t],
                   &reinterpret_cast<const float4*>(g_bufA + c * NSP + base)[q]);
    }
    for (int t = tid; t < 3136; t += NT)
        cp_async16(&reinterpret_cast<float4*>(sW)[t],
                   &reinterpret_cast<const float4*>(g_W3eff)[t]);
    cp_commit();
    cp_wait0();
    __syncthreads();
    int row0 = (tid >> 5) * 8, px = (tid & 31) * 4;
    float2 acc[8][2];
#pragma unroll
    for (int r = 0; r < 8; r++) {
        float b = g_B3tot[row0 + r];
        acc[r][0] = make_float2(b, b); acc[r][1] = make_float2(b, b);
    }
    mma_core(sIn, sW, row0, px, acc);
    float fs = 0.f, fq = 0.f;
#pragma unroll
    for (int r = 0; r < 8; r++) {
        int o = row0 + r;
        float rr = g_r0[o];
        float4 xv = *reinterpret_cast<const float4*>(x + o * NSP + base + px);
        float4 v = make_float4(acc[r][0].x + xv.x * rr, acc[r][0].y + xv.y * rr,
                               acc[r][1].x + xv.z * rr, acc[r][1].y + xv.w * rr);
        *reinterpret_cast<float4*>(g_bufB + o * NSP + base + px) = v;
        fs += v.x + v.y + v.z + v.w;
        fq += v.x * v.x + v.y * v.y + v.z * v.z + v.w * v.w;
    }
    block_part(fs, fq, g_part3);
}

// ---------------- F3: gn(n2) -> fold into fc1 ----------------
__global__ void f3_fin(const float* __restrict__ fc1w, const float* __restrict__ fc1b,
                       const float* __restrict__ n2g, const float* __restrict__ n2b) {
    __shared__ float mr[2];
    __shared__ float s3s[CC], t3s[CC];
    stats_reduce(g_part3, NBLK, mr);
    int tid = threadIdx.x;
    if (tid < CC) {
        float sc = mr[1] * n2g[tid];
        s3s[tid] = sc;
        t3s[tid] = n2b[tid] - mr[0] * sc;
    }
    __syncthreads();
    for (int t = tid; t < HID * CC; t += 256) g_W4eff[t] = fc1w[t] * s3s[t % CC];
    for (int hh = tid; hh < HID; hh += 256) {
        float acc = fc1b[hh];
#pragma unroll 4
        for (int c = 0; c < CC; c++) acc += fc1w[hh * CC + c] * t3s[c];
        g_B4eff[hh] = acc;
    }
}

// ---------------- K6: fused MLP with double-buffered cp.async weight pipeline ----------------
// 8 phases (fc1[0],fc2[0],fc1[1],fc2[1],...): prefetch chunk p+1 into the idle
// weight buffer while computing chunk p. 1 barrier + 1 wait per phase.
__global__ __launch_bounds__(NT) void k6_mlp(const float* __restrict__ fc2w,
                                             const float* __restrict__ fc2b,
                                             float* __restrict__ out) {
    extern __shared__ float sm[];
    float* xt  = sm;                    // [112][128] x1 tile (residual source)
    float* hc  = sm + CC * 128;         // [112][128] hidden chunk
    float* wb0 = hc + CC * 128;         // [112][112]
    float* wb1 = wb0 + CC * CC;         // [112][112]
    int tid = threadIdx.x;
    int base = blockIdx.x * 128;

    // prologue: async stage xt + first fc1 weight chunk
    for (int t = tid; t < CC * 32; t += NT) {
        int c = t >> 5, q = t & 31;
        cp_async16(&reinterpret_cast<float4*>(xt)[t],
                   &reinterpret_cast<const float4*>(g_bufB + c * NSP + base)[q]);
    }
    for (int t = tid; t < 3136; t += NT)
        cp_async16(&reinterpret_cast<float4*>(wb0)[t],
                   &reinterpret_cast<const float4*>(g_W4eff)[t]);
    cp_commit();

    int row0 = (tid >> 5) * 8, px = (tid & 31) * 4;
    float2 oacc[8][2];
#pragma unroll
    for (int r = 0; r < 8; r++) {
        float b = fc2b[row0 + r];
        oacc[r][0] = make_float2(b, b); oacc[r][1] = make_float2(b, b);
    }

    cp_wait0();
    __syncthreads();

#pragma unroll 1
    for (int p = 0; p < 8; p++) {
        float* cur = (p & 1) ? wb1 : wb0;
        float* nxt = (p & 1) ? wb0 : wb1;
        int hb = p >> 1;
        // prefetch chunk p+1 into nxt (its last readers finished before the
        // barrier that ended phase p-1)
        if (p < 7) {
            int np = p + 1, nhb = np >> 1;
            if ((np & 1) == 0) {          // next is fc1 chunk nhb
                for (int t = tid; t < 3136; t += NT)
                    cp_async16(&reinterpret_cast<float4*>(nxt)[t],
                               &reinterpret_cast<const float4*>(g_W4eff)[nhb * 3136 + t]);
            } else {                      // next is fc2 chunk nhb
                for (int t = tid; t < 3136; t += NT) {
                    int o = t / 28, kq = t % 28;
                    cp_async16(&reinterpret_cast<float4*>(nxt)[t],
                               &reinterpret_cast<const float4*>(fc2w)[o * 112 + nhb * 28 + kq]);
                }
            }
            cp_commit();
        }
        if ((p & 1) == 0) {               // fc1 phase: hc = gelu(W4eff[hb] @ xt + b)
            float2 acc[8][2];
#pragma unroll
            for (int r = 0; r < 8; r++) {
                float b = g_B4eff[hb * CC + row0 + r];
                acc[r][0] = make_float2(b, b); acc[r][1] = make_float2(b, b);
            }
            mma_core(xt, cur, row0, px, acc);
#pragma unroll
            for (int r = 0; r < 8; r++) {
                float4 v = make_float4(gelu_f(acc[r][0].x), gelu_f(acc[r][0].y),
                                       gelu_f(acc[r][1].x), gelu_f(acc[r][1].y));
                *reinterpret_cast<float4*>(hc + (row0 + r) * 128 + px) = v;
            }
        } else {                          // fc2 phase: oacc += fc2[hb] @ hc
            mma_core(hc, cur, row0, px, oacc);
        }
        if (p < 7) cp_wait0();            // prefetch landed (overlapped with mma)
        __syncthreads();                  // orders hc writes/reads + buffer reuse
    }
#pragma unroll
    for (int r = 0; r < 8; r++) {
        float4 xv = *reinterpret_cast<const float4*>(xt + (row0 + r) * 128 + px);
        float4 v = make_float4(oacc[r][0].x + xv.x, oacc[r][0].y + xv.y,
                               oacc[r][1].x + xv.z, oacc[r][1].y + xv.w);
        *reinterpret_cast<float4*>(out + (row0 + r) * NSP + base + px) = v;
    }
}

// ---------------- launch ----------------
extern "C" void kernel_launch(void* const* d_in, const int* in_sizes, int n_in,
                              void* d_out, int out_size) {
    const float* x    = (const float*)d_in[0];
    const float* c1w  = (const float*)d_in[1];
    const float* c1b  = (const float*)d_in[2];
    const float* c2dw = (const float*)d_in[3];
    const float* c2db = (const float*)d_in[4];
    const float* c2hw = (const float*)d_in[5];
    const float* c2hb = (const float*)d_in[6];
    const float* c2ww = (const float*)d_in[7];
    const float* c2wb = (const float*)d_in[8];
    const float* c3w  = (const float*)d_in[9];
    const float* c3b  = (const float*)d_in[10];
    const float* fc1w = (const float*)d_in[11];
    const float* fc1b = (const float*)d_in[12];
    const float* fc2w = (const float*)d_in[13];
    const float* fc2b = (const float*)d_in[14];
    const float* n1g  = (const float*)d_in[15];
    const float* n1b  = (const float*)d_in[16];
    const float* na1g = (const float*)d_in[17];
    const float* na1b = (const float*)d_in[18];
    const float* na2g = (const float*)d_in[19];
    const float* na2b = (const float*)d_in[20];
    const float* n2g  = (const float*)d_in[21];
    const float* n2b  = (const float*)d_in[22];
    float* out = (float*)d_out;

    static bool attr_done = false;
    if (!attr_done) {
        cudaFuncSetAttribute(k1_conv1, cudaFuncAttributeMaxDynamicSharedMemorySize, GEMM_SMEM);
        cudaFuncSetAttribute(k3_axial, cudaFuncAttributeMaxDynamicSharedMemorySize, PIPE_SMEM);
        cudaFuncSetAttribute(k5_conv3, cudaFuncAttributeMaxDynamicSharedMemorySize, GEMM_SMEM);
        cudaFuncSetAttribute(k6_mlp,   cudaFuncAttributeMaxDynamicSharedMemorySize, PIPE_SMEM);
        attr_done = true;
    }

    k0_stats<<<1024, 256>>>(x);
    f0_fin<<<1, 256>>>(c1w, c1b, n1g, n1b);
    k1_conv1<<<NBLK, NT, GEMM_SMEM>>>(x);                 // u -> bufA
    f1_fin<<<1, 256>>>(na1g, na1b);
    k2_act<<<28672, 256>>>();                             // a -> bufB
    k3_axial<<<NBLK, NT, PIPE_SMEM>>>(c2dw, c2db, c2hw, c2hb, c2ww, c2wb);  // s -> bufA
    f2_fin<<<1, 256>>>(c3w, c3b, na2g, na2b);
    k5_conv3<<<NBLK, NT, GEMM_SMEM>>>(x);                 // x1 -> bufB
    f3_fin<<<1, 256>>>(fc1w, fc1b, n2g, n2b);
    k6_mlp<<<NBLK, NT, PIPE_SMEM>>>(fc2w, fc2b, out);
}

// round 17
// speedup vs baseline: 1.2699x; 1.0035x over previous
#include <cuda_runtime.h>

#define CC   112
#define NSP  262144                     // 64^3 spatial positions
#define MTOT (CC*NSP)                   // 29360128
#define HID  448
#define NT   448                        // 14 warps x 8 rows, 128 pos
#define NBLK 2048                       // 128-pos tiles
#define PIPE_SMEM ((2*CC*128 + 2*CC*CC)*4)      // 215040 B
#define DBIN_SMEM ((2*CC*128 + CC*CC)*4)        // 164864 B (2x sIn + 1x sW)

// ---------------- scratch (static device memory; no allocations) ----------------
__device__ float g_bufA[MTOT];          // u, then s(branch-sum)
__device__ float g_bufB[MTOT];          // a, then x1
__device__ double2 g_part0[1024];
__device__ double2 g_part1[4096];
__device__ double2 g_part2[4096];
__device__ double2 g_part3[4096];
__device__ int   g_cnt[4];              // last-block tickets (reset by last block)
__device__ float g_s0[CC], g_t0[CC], g_r0[CC];
__device__ float g_s1[CC], g_t1[CC];
__device__ float g_W1eff[CC*CC], g_B1eff[CC];
__device__ float g_W3eff[CC*CC], g_B3tot[CC];
__device__ float g_W4eff[HID*CC], g_B4eff[HID];

// ---------------- helpers ----------------
__device__ __forceinline__ float2 ffma2(float2 a, float2 b, float2 c) {
    unsigned long long ua = *reinterpret_cast<unsigned long long*>(&a);
    unsigned long long ub = *reinterpret_cast<unsigned long long*>(&b);
    unsigned long long uc = *reinterpret_cast<unsigned long long*>(&c);
    unsigned long long ud;
    asm("fma.rn.f32x2 %0, %1, %2, %3;" : "=l"(ud) : "l"(ua), "l"(ub), "l"(uc));
    return *reinterpret_cast<float2*>(&ud);
}

__device__ __forceinline__ float gelu_f(float v) {
    return 0.5f * v * (1.0f + erff(v * 0.7071067811865476f));
}

__device__ __forceinline__ void cp_async16(float4* dst_smem, const float4* src) {
    unsigned s = (unsigned)__cvta_generic_to_shared(dst_smem);
    asm volatile("cp.async.cg.shared.global [%0], [%1], 16;" :: "r"(s), "l"(src));
}
__device__ __forceinline__ void cp_async4_pred(float* dst_smem, const float* src, bool valid) {
    unsigned s = (unsigned)__cvta_generic_to_shared(dst_smem);
    int sz = valid ? 4 : 0;
    asm volatile("cp.async.ca.shared.global [%0], [%1], 4, %2;"
                 :: "r"(s), "l"(src), "r"(sz));
}
__device__ __forceinline__ void cp_commit() { asm volatile("cp.async.commit_group;"); }
__device__ __forceinline__ void cp_wait0()  { asm volatile("cp.async.wait_group 0;" ::: "memory"); }
template<int N> __device__ __forceinline__ void cp_waitN() {
    asm volatile("cp.async.wait_group %0;" :: "n"(N) : "memory");
}

// register-tiled GEMM core: 8 rows x 4 positions per thread; row0 warp-uniform
// -> weight LDS.128 are address-uniform broadcasts.
__device__ __forceinline__ void mma_core(const float* __restrict__ sIn,
                                         const float* __restrict__ sW,
                                         int row0, int px, float2 (&acc)[8][2]) {
#pragma unroll 1
    for (int k0 = 0; k0 < CC; k0 += 4) {
        float4 wv[8];
#pragma unroll
        for (int r = 0; r < 8; r++)
            wv[r] = *reinterpret_cast<const float4*>(sW + (row0 + r) * CC + k0);
#pragma unroll
        for (int kk = 0; kk < 4; kk++) {
            float4 xv = *reinterpret_cast<const float4*>(sIn + (k0 + kk) * 128 + px);
            float2 xa = make_float2(xv.x, xv.y);
            float2 xb = make_float2(xv.z, xv.w);
#pragma unroll
            for (int r = 0; r < 8; r++) {
                float w = (kk == 0) ? wv[r].x : (kk == 1) ? wv[r].y
                        : (kk == 2) ? wv[r].z : wv[r].w;
                float2 wd = make_float2(w, w);
                acc[r][0] = ffma2(xa, wd, acc[r][0]);
                acc[r][1] = ffma2(xb, wd, acc[r][1]);
            }
        }
    }
}

// block partial (sum, sumsq) -> out[blockIdx.x]; supports up to 16 warps
__device__ __forceinline__ void block_part(float fs, float fq, double2* out) {
    double s = fs, q = fq;
#pragma unroll
    for (int o = 16; o; o >>= 1) {
        s += __shfl_down_sync(0xffffffffu, s, o);
        q += __shfl_down_sync(0xffffffffu, q, o);
    }
    __shared__ double ws[16], wq[16];
    int w = threadIdx.x >> 5, l = threadIdx.x & 31;
    if (!l) { ws[w] = s; wq[w] = q; }
    __syncthreads();
    if (!threadIdx.x) {
        double ts = 0, tq = 0;
        int nw = blockDim.x >> 5;
        for (int i = 0; i < nw; i++) { ts += ws[i]; tq += wq[i]; }
        out[blockIdx.x] = make_double2(ts, tq);
    }
}

// last-block election (threadfence-reduction pattern); resets its own ticket.
__device__ __forceinline__ bool last_block(int idx) {
    __shared__ int lastf;
    if (!threadIdx.x) {
        __threadfence();
        lastf = (atomicAdd(&g_cnt[idx], 1) == (int)gridDim.x - 1);
        if (lastf) g_cnt[idx] = 0;       // reset for next graph replay
    }
    __syncthreads();
    if (lastf) __threadfence();          // acquire partials
    return lastf;
}

// reduce partials -> (mean, rstd) via shared mr[2]; any blockDim (mult of 32, <=512)
__device__ __forceinline__ void stats_reduce(const double2* part, int n, float* mr) {
    int tid = threadIdx.x, nt = blockDim.x;
    double s = 0, q = 0;
    for (int i = tid; i < n; i += nt) { s += part[i].x; q += part[i].y; }
#pragma unroll
    for (int o = 16; o; o >>= 1) {
        s += __shfl_down_sync(0xffffffffu, s, o);
        q += __shfl_down_sync(0xffffffffu, q, o);
    }
    __shared__ double ws[16], wq[16];
    int w = tid >> 5, l = tid & 31;
    if (!l) { ws[w] = s; wq[w] = q; }
    __syncthreads();
    if (!tid) {
        double ts = 0, tq = 0;
        int nw = nt >> 5;
        for (int i = 0; i < nw; i++) { ts += ws[i]; tq += wq[i]; }
        double mean = ts / (double)MTOT;
        double var  = tq / (double)MTOT - mean * mean;
        mr[0] = (float)mean;
        mr[1] = (float)rsqrt(var + 1e-5);
    }
    __syncthreads();
}

// ---------------- K0: stats of x, last block folds gn1 into conv1 (old f0) ----------------
__global__ void k0_stats(const float* __restrict__ x,
                         const float* __restrict__ c1w, const float* __restrict__ c1b,
                         const float* __restrict__ n1g, const float* __restrict__ n1b) {
    int gtid = blockIdx.x * blockDim.x + threadIdx.x;
    const float4* x4 = reinterpret_cast<const float4*>(x);
    float fs = 0.f, fq = 0.f;
    for (int i = gtid; i < MTOT / 4; i += 262144) {
        float4 v = x4[i];
        fs += v.x + v.y + v.z + v.w;
        fq += fmaf(v.x, v.x, fmaf(v.y, v.y, fmaf(v.z, v.z, v.w * v.w)));
    }
    block_part(fs, fq, g_part0);
    if (!last_block(0)) return;
    // ---- fused f0 ----
    __shared__ float mr[2];
    __shared__ float t0s[CC];
    stats_reduce(g_part0, 1024, mr);
    int tid = threadIdx.x;
    if (tid < CC) {
        float sc = mr[1] * n1g[tid];
        float tt = n1b[tid] - mr[0] * sc;
        g_s0[tid] = sc;
        g_t0[tid] = tt;
        t0s[tid]  = tt;
        g_r0[tid] = 1.0f + sc;
    }
    __syncthreads();
    for (int t = tid; t < CC * CC; t += 256) g_W1eff[t] = c1w[t] * g_s0[t % CC];
    if (tid < CC) {
        float acc = c1b[tid];
#pragma unroll 4
        for (int c = 0; c < CC; c++) acc += c1w[tid * CC + c] * t0s[c];
        g_B1eff[tid] = acc;
    }
}

// ---------------- K1: u = conv1(gn1(x)) -> bufA; 2 tiles/block, double-buffered in;
//                  last block computes gn(na1) params (old f1) ----------------
__global__ __launch_bounds__(NT) void k1_conv1(const float* __restrict__ x,
                                               const float* __restrict__ na1g,
                                               const float* __restrict__ na1b) {
    extern __shared__ float sm[];
    float* sIn0 = sm;                    // [112][128]
    float* sIn1 = sIn0 + CC * 128;
    float* sW   = sIn1 + CC * 128;       // [112][112]
    int tid = threadIdx.x;
    int base0 = blockIdx.x * 256;
    // prologue: weights + tile0 input (group 0)
    for (int t = tid; t < 3136; t += NT)
        cp_async16(&reinterpret_cast<float4*>(sW)[t],
                   &reinterpret_cast<const float4*>(g_W1eff)[t]);
    for (int t = tid; t < CC * 32; t += NT) {
        int c = t >> 5, q = t & 31;
        cp_async16(&reinterpret_cast<float4*>(sIn0)[t],
                   &reinterpret_cast<const float4*>(x + c * NSP + base0)[q]);
    }
    cp_commit();
    // prefetch tile1 input (group 1)
    for (int t = tid; t < CC * 32; t += NT) {
        int c = t >> 5, q = t & 31;
        cp_async16(&reinterpret_cast<float4*>(sIn1)[t],
                   &reinterpret_cast<const float4*>(x + c * NSP + base0 + 128)[q]);
    }
    cp_commit();

    int row0 = (tid >> 5) * 8, px = (tid & 31) * 4;
    float fs = 0.f, fq = 0.f;
#pragma unroll 1
    for (int t = 0; t < 2; t++) {
        if (t == 0) cp_waitN<1>(); else cp_wait0();
        __syncthreads();
        const float* cin = t ? sIn1 : sIn0;
        int base = base0 + t * 128;
        float2 acc[8][2];
#pragma unroll
        for (int r = 0; r < 8; r++) {
            float b = g_B1eff[row0 + r];
            acc[r][0] = make_float2(b, b); acc[r][1] = make_float2(b, b);
        }
        mma_core(cin, sW, row0, px, acc);
#pragma unroll
        for (int r = 0; r < 8; r++) {
            float4 v = make_float4(acc[r][0].x, acc[r][0].y, acc[r][1].x, acc[r][1].y);
            *reinterpret_cast<float4*>(g_bufA + (row0 + r) * NSP + base + px) = v;
            fs += v.x + v.y + v.z + v.w;
            fq += v.x * v.x + v.y * v.y + v.z * v.z + v.w * v.w;
        }
    }
    block_part(fs, fq, g_part1);
    if (!last_block(1)) return;
    // ---- fused f1 ----
    __shared__ float mr[2];
    stats_reduce(g_part1, 1024, mr);
    if (tid < CC) {
        float sc = mr[1] * na1g[tid];
        g_s1[tid] = sc;
        g_t1[tid] = na1b[tid] - mr[0] * sc;
    }
}

// ---------------- K2: a = gelu(gn_na1(u)) : bufA -> bufB ----------------
__global__ void k2_act() {
    int i = blockIdx.x * 256 + threadIdx.x;   // 28672 blocks * 256 = MTOT/4
    float4 v = reinterpret_cast<const float4*>(g_bufA)[i];
    int c = i >> 16;                           // NSP/4 = 65536 float4 per channel
    float sc = g_s1[c], tt = g_t1[c];
    v.x = gelu_f(fmaf(v.x, sc, tt));
    v.y = gelu_f(fmaf(v.y, sc, tt));
    v.z = gelu_f(fmaf(v.z, sc, tt));
    v.w = gelu_f(fmaf(v.w, sc, tt));
    reinterpret_cast<float4*>(g_bufB)[i] = v;
}

// ---------------- K3: three axial-shift branch GEMMs, pipelined; last block
//                  folds gn(na2) into conv3 (old f2) ----------------
__global__ __launch_bounds__(NT) void k3_axial(
    const float* __restrict__ w2d, const float* __restrict__ b2d,
    const float* __restrict__ w2h, const float* __restrict__ b2h,
    const float* __restrict__ w2w, const float* __restrict__ b2w,
    const float* __restrict__ c3w, const float* __restrict__ c3b,
    const float* __restrict__ na2g, const float* __restrict__ na2b) {
    extern __shared__ float sm[];
    float* sIn0 = sm;                    // [112][128]
    float* sIn1 = sIn0 + CC * 128;
    float* wb0  = sIn1 + CC * 128;       // [112][112]
    float* wb1  = wb0 + CC * CC;
    int tid = threadIdx.x;
    int d  = blockIdx.x >> 5;                 // 32 blocks per d-slice
    int h0 = (blockIdx.x & 31) * 2;           // two h rows per block
    int base = blockIdx.x * 128;
    int row0 = (tid >> 5) * 8, px = (tid & 31) * 4;

    // prologue: prefetch branch 0 (weights + gather)
    for (int t = tid; t < 3136; t += NT)
        cp_async16(&reinterpret_cast<float4*>(wb0)[t],
                   &reinterpret_cast<const float4*>(w2d)[t]);
    for (int t = tid; t < CC * 128; t += NT) {
        int c = t >> 7, j = t & 127;
        int hh = h0 + (j >> 6), w = j & 63;
        int ch = c >> 4;                      // chunk i = c/16
        int dd = d + 3 - ch;                  // a[c, d+3-i, hh, w]
        bool valid = ((unsigned)dd < 64u);
        int idx = valid ? (c * NSP + dd * 4096 + hh * 64 + w) : 0;
        cp_async4_pred(&sIn0[t], g_bufB + idx, valid);
    }
    cp_commit();

    float2 sum[8][2];
#pragma unroll
    for (int r = 0; r < 8; r++) {
        sum[r][0] = make_float2(0.f, 0.f); sum[r][1] = make_float2(0.f, 0.f);
    }
    cp_wait0();
    __syncthreads();

#pragma unroll 1
    for (int br = 0; br < 3; br++) {
        float* curIn = (br & 1) ? sIn1 : sIn0;
        float* curW  = (br & 1) ? wb1  : wb0;
        if (br < 2) {
            float* nIn = (br & 1) ? sIn0 : sIn1;
            float* nW  = (br & 1) ? wb0  : wb1;
            const float* wsrc = (br == 0) ? w2h : w2w;
            for (int t = tid; t < 3136; t += NT)
                cp_async16(&reinterpret_cast<float4*>(nW)[t],
                           &reinterpret_cast<const float4*>(wsrc)[t]);
            for (int t = tid; t < CC * 128; t += NT) {
                int c = t >> 7, j = t & 127;
                int hh = h0 + (j >> 6), w = j & 63;
                int ch = c >> 4;
                bool valid; int idx = 0;
                if (br == 0) {                    // next: a[c, d-3, hh-i, w-3]
                    int h2 = hh - ch;
                    valid = (d >= 3 && h2 >= 0 && w >= 3);
                    if (valid) idx = c * NSP + (d - 3) * 4096 + h2 * 64 + (w - 3);
                } else {                          // next: a[c, d-6, hh-6, w-3-i]
                    int ww = w - 3 - ch;
                    valid = (d >= 6 && hh >= 6 && ww >= 0);
                    if (valid) idx = c * NSP + (d - 6) * 4096 + (hh - 6) * 64 + ww;
                }
                cp_async4_pred(&nIn[t], g_bufB + idx, valid);
            }
            cp_commit();
        }
        const float* bsrc = (br == 0) ? b2d : (br == 1) ? b2h : b2w;
        float2 acc[8][2];
#pragma unroll
        for (int r = 0; r < 8; r++) {
            float b = bsrc[row0 + r];
            acc[r][0] = make_float2(b, b); acc[r][1] = make_float2(b, b);
        }
        mma_core(curIn, curW, row0, px, acc);
#pragma unroll
        for (int r = 0; r < 8; r++) {
            sum[r][0].x += gelu_f(acc[r][0].x);
            sum[r][0].y += gelu_f(acc[r][0].y);
            sum[r][1].x += gelu_f(acc[r][1].x);
            sum[r][1].y += gelu_f(acc[r][1].y);
        }
        if (br < 2) cp_wait0();           // prefetch landed (overlapped with mma)
        __syncthreads();                  // buffer-reuse ordering
    }
    float fs = 0.f, fq = 0.f;
#pragma unroll
    for (int r = 0; r < 8; r++) {
        float4 v = make_float4(sum[r][0].x, sum[r][0].y, sum[r][1].x, sum[r][1].y);
        *reinterpret_cast<float4*>(g_bufA + (row0 + r) * NSP + base + px) = v;
        fs += v.x + v.y + v.z + v.w;
        fq += v.x * v.x + v.y * v.y + v.z * v.z + v.w * v.w;
    }
    block_part(fs, fq, g_part2);
    if (!last_block(2)) return;
    // ---- fused f2 ----
    __shared__ float mr[2];
    __shared__ float s2s[CC], t2s[CC];
    stats_reduce(g_part2, NBLK, mr);
    if (tid < CC) {
        float sc = mr[1] * na2g[tid];
        s2s[tid] = sc;
        t2s[tid] = na2b[tid] - mr[0] * sc;
    }
    __syncthreads();
    for (int t = tid; t < CC * CC; t += NT) g_W3eff[t] = c3w[t] * s2s[t % CC];
    if (tid < CC) {
        float acc = c3b[tid];
#pragma unroll 4
        for (int c = 0; c < CC; c++) acc += c3w[tid * CC + c] * t2s[c];
        g_B3tot[tid] = acc + g_t0[tid];   // + h0 bias term
    }
}

// ---------------- K5: x1 = conv3(gn_na2(s)) + h0 + x : bufA -> bufB;
//                  2 tiles/block, double-buffered in; last block folds gn(n2)
//                  into fc1 (old f3) ----------------
__global__ __launch_bounds__(NT) void k5_conv3(const float* __restrict__ x,
                                               const float* __restrict__ fc1w,
                                               const float* __restrict__ fc1b,
                                               const float* __restrict__ n2g,
                                               const float* __restrict__ n2b) {
    extern __shared__ float sm[];
    float* sIn0 = sm;
    float* sIn1 = sIn0 + CC * 128;
    float* sW   = sIn1 + CC * 128;
    int tid = threadIdx.x;
    int base0 = blockIdx.x * 256;
    for (int t = tid; t < 3136; t += NT)
        cp_async16(&reinterpret_cast<float4*>(sW)[t],
                   &reinterpret_cast<const float4*>(g_W3eff)[t]);
    for (int t = tid; t < CC * 32; t += NT) {
        int c = t >> 5, q = t & 31;
        cp_async16(&reinterpret_cast<float4*>(sIn0)[t],
                   &reinterpret_cast<const float4*>(g_bufA + c * NSP + base0)[q]);
    }
    cp_commit();
    for (int t = tid; t < CC * 32; t += NT) {
        int c = t >> 5, q = t & 31;
        cp_async16(&reinterpret_cast<float4*>(sIn1)[t],
                   &reinterpret_cast<const float4*>(g_bufA + c * NSP + base0 + 128)[q]);
    }
    cp_commit();

    int row0 = (tid >> 5) * 8, px = (tid & 31) * 4;
    float fs = 0.f, fq = 0.f;
#pragma unroll 1
    for (int t = 0; t < 2; t++) {
        if (t == 0) cp_waitN<1>(); else cp_wait0();
        __syncthreads();
        const float* cin = t ? sIn1 : sIn0;
        int base = base0 + t * 128;
        float2 acc[8][2];
#pragma unroll
        for (int r = 0; r < 8; r++) {
            float b = g_B3tot[row0 + r];
            acc[r][0] = make_float2(b, b); acc[r][1] = make_float2(b, b);
        }
        mma_core(cin, sW, row0, px, acc);
#pragma unroll
        for (int r = 0; r < 8; r++) {
            int o = row0 + r;
            float rr = g_r0[o];
            float4 xv = *reinterpret_cast<const float4*>(x + o * NSP + base + px);
            float4 v = make_float4(acc[r][0].x + xv.x * rr, acc[r][0].y + xv.y * rr,
                                   acc[r][1].x + xv.z * rr, acc[r][1].y + xv.w * rr);
            *reinterpret_cast<float4*>(g_bufB + o * NSP + base + px) = v;
            fs += v.x + v.y + v.z + v.w;
            fq += v.x * v.x + v.y * v.y + v.z * v.z + v.w * v.w;
        }
    }
    block_part(fs, fq, g_part3);
    if (!last_block(3)) return;
    // ---- fused f3 ----
    __shared__ float mr[2];
    __shared__ float s3s[CC], t3s[CC];
    stats_reduce(g_part3, 1024, mr);
    if (tid < CC) {
        float sc = mr[1] * n2g[tid];
        s3s[tid] = sc;
        t3s[tid] = n2b[tid] - mr[0] * sc;
    }
    __syncthreads();
    for (int t = tid; t < HID * CC; t += NT) g_W4eff[t] = fc1w[t] * s3s[t % CC];
    for (int hh = tid; hh < HID; hh += NT) {
        float acc = fc1b[hh];
#pragma unroll 4
        for (int c = 0; c < CC; c++) acc += fc1w[hh * CC + c] * t3s[c];
        g_B4eff[hh] = acc;
    }
}

// ---------------- K6: fused MLP with double-buffered cp.async weight pipeline ----------------
__global__ __launch_bounds__(NT) void k6_mlp(const float* __restrict__ fc2w,
                                             const float* __restrict__ fc2b,
                                             float* __restrict__ out) {
    extern __shared__ float sm[];
    float* xt  = sm;                    // [112][128] x1 tile (residual source)
    float* hc  = sm + CC * 128;         // [112][128] hidden chunk
    float* wb0 = hc + CC * 128;         // [112][112]
    float* wb1 = wb0 + CC * CC;         // [112][112]
    int tid = threadIdx.x;
    int base = blockIdx.x * 128;

    for (int t = tid; t < CC * 32; t += NT) {
        int c = t >> 5, q = t & 31;
        cp_async16(&reinterpret_cast<float4*>(xt)[t],
                   &reinterpret_cast<const float4*>(g_bufB + c * NSP + base)[q]);
    }
    for (int t = tid; t < 3136; t += NT)
        cp_async16(&reinterpret_cast<float4*>(wb0)[t],
                   &reinterpret_cast<const float4*>(g_W4eff)[t]);
    cp_commit();

    int row0 = (tid >> 5) * 8, px = (tid & 31) * 4;
    float2 oacc[8][2];
#pragma unroll
    for (int r = 0; r < 8; r++) {
        float b = fc2b[row0 + r];
        oacc[r][0] = make_float2(b, b); oacc[r][1] = make_float2(b, b);
    }

    cp_wait0();
    __syncthreads();

#pragma unroll 1
    for (int p = 0; p < 8; p++) {
        float* cur = (p & 1) ? wb1 : wb0;
        float* nxt = (p & 1) ? wb0 : wb1;
        int hb = p >> 1;
        if (p < 7) {
            int np = p + 1, nhb = np >> 1;
            if ((np & 1) == 0) {          // next is fc1 chunk nhb
                for (int t = tid; t < 3136; t += NT)
                    cp_async16(&reinterpret_cast<float4*>(nxt)[t],
                               &reinterpret_cast<const float4*>(g_W4eff)[nhb * 3136 + t]);
            } else {                      // next is fc2 chunk nhb
                for (int t = tid; t < 3136; t += NT) {
                    int o = t / 28, kq = t % 28;
                    cp_async16(&reinterpret_cast<float4*>(nxt)[t],
                               &reinterpret_cast<const float4*>(fc2w)[o * 112 + nhb * 28 + kq]);
                }
            }
            cp_commit();
        }
        if ((p & 1) == 0) {               // fc1 phase: hc = gelu(W4eff[hb] @ xt + b)
            float2 acc[8][2];
#pragma unroll
            for (int r = 0; r < 8; r++) {
                float b = g_B4eff[hb * CC + row0 + r];
                acc[r][0] = make_float2(b, b); acc[r][1] = make_float2(b, b);
            }
            mma_core(xt, cur, row0, px, acc);
#pragma unroll
            for (int r = 0; r < 8; r++) {
                float4 v = make_float4(gelu_f(acc[r][0].x), gelu_f(acc[r][0].y),
                                       gelu_f(acc[r][1].x), gelu_f(acc[r][1].y));
                *reinterpret_cast<float4*>(hc + (row0 + r) * 128 + px) = v;
            }
        } else {                          // fc2 phase: oacc += fc2[hb] @ hc
            mma_core(hc, cur, row0, px, oacc);
        }
        if (p < 7) cp_wait0();
        __syncthreads();
    }
#pragma unroll
    for (int r = 0; r < 8; r++) {
        float4 xv = *reinterpret_cast<const float4*>(xt + (row0 + r) * 128 + px);
        float4 v = make_float4(oacc[r][0].x + xv.x, oacc[r][0].y + xv.y,
                               oacc[r][1].x + xv.z, oacc[r][1].y + xv.w);
        *reinterpret_cast<float4*>(out + (row0 + r) * NSP + base + px) = v;
    }
}

// ---------------- launch ----------------
extern "C" void kernel_launch(void* const* d_in, const int* in_sizes, int n_in,
                              void* d_out, int out_size) {
    const float* x    = (const float*)d_in[0];
    const float* c1w  = (const float*)d_in[1];
    const float* c1b  = (const float*)d_in[2];
    const float* c2dw = (const float*)d_in[3];
    const float* c2db = (const float*)d_in[4];
    const float* c2hw = (const float*)d_in[5];
    const float* c2hb = (const float*)d_in[6];
    const float* c2ww = (const float*)d_in[7];
    const float* c2wb = (const float*)d_in[8];
    const float* c3w  = (const float*)d_in[9];
    const float* c3b  = (const float*)d_in[10];
    const float* fc1w = (const float*)d_in[11];
    const float* fc1b = (const float*)d_in[12];
    const float* fc2w = (const float*)d_in[13];
    const float* fc2b = (const float*)d_in[14];
    const float* n1g  = (const float*)d_in[15];
    const float* n1b  = (const float*)d_in[16];
    const float* na1g = (const float*)d_in[17];
    const float* na1b = (const float*)d_in[18];
    const float* na2g = (const float*)d_in[19];
    const float* na2b = (const float*)d_in[20];
    const float* n2g  = (const float*)d_in[21];
    const float* n2b  = (const float*)d_in[22];
    float* out = (float*)d_out;

    static bool attr_done = false;
    if (!attr_done) {
        cudaFuncSetAttribute(k1_conv1, cudaFuncAttributeMaxDynamicSharedMemorySize, DBIN_SMEM);
        cudaFuncSetAttribute(k3_axial, cudaFuncAttributeMaxDynamicSharedMemorySize, PIPE_SMEM);
        cudaFuncSetAttribute(k5_conv3, cudaFuncAttributeMaxDynamicSharedMemorySize, DBIN_SMEM);
        cudaFuncSetAttribute(k6_mlp,   cudaFuncAttributeMaxDynamicSharedMemorySize, PIPE_SMEM);
        attr_done = true;
    }

    k0_stats<<<1024, 256>>>(x, c1w, c1b, n1g, n1b);                 // + fused f0
    k1_conv1<<<1024, NT, DBIN_SMEM>>>(x, na1g, na1b);               // u -> bufA, + fused f1
    k2_act<<<28672, 256>>>();                                       // a -> bufB
    k3_axial<<<NBLK, NT, PIPE_SMEM>>>(c2dw, c2db, c2hw, c2hb, c2ww, c2wb,
                                      c3w, c3b, na2g, na2b);        // s -> bufA, + fused f2
    k5_conv3<<<1024, NT, DBIN_SMEM>>>(x, fc1w, fc1b, n2g, n2b);     // x1 -> bufB, + fused f3
    k6_mlp<<<NBLK, NT, PIPE_SMEM>>>(fc2w, fc2b, out);
}